// round 10
// baseline (speedup 1.0000x reference)
#include <cuda_runtime.h>
#include <cuda_bf16.h>
#include <math_constants.h>
#include <cstdint>

#define NMAX 50176
#define EMAX 800000
#define D    128
#define D2   256
#define MSG_EPS 1e-7f
#define SM_EPS  1e-16f
#define BN_EPS  1e-5f
#define LN_EPS  1e-5f
#define NPARTMAX 64

// ---------------- scratch (static device globals; no allocation) -------------
__device__ int   g_deg[NMAX];          // always zero at launch entry (reset by scan_local)
__device__ int   g_offs[NMAX + 1];
__device__ int   g_cur[NMAX];
__device__ int   g_srcs[EMAX];
__device__ int   g_partoffs[NPARTMAX];
__device__ int   g_done1;              // reset by K1 last block
__device__ int   g_done2;              // reset by gemm1 last CTA
__device__ float g_h1[(size_t)NMAX * D2];
__device__ float g_colsum[D2];         // zero at entry (reset by gemm1 last CTA)
__device__ float g_colsq[D2];
__device__ float g_bnscale[D2];
__device__ float g_bnshift[D2];
__device__ __align__(16) unsigned char g_W1img_hi[69632];
__device__ __align__(16) unsigned char g_W1img_lo[69632];
__device__ __align__(16) unsigned char g_W2img_hi[69632];
__device__ __align__(16) unsigned char g_W2img_lo[69632];

// ---------------- helpers ----------------------------------------------------
__device__ __forceinline__ uint32_t smem_u32(const void* p) {
    uint32_t a;
    asm("{ .reg .u64 t; cvta.to.shared.u64 t, %1; cvt.u32.u64 %0, t; }" : "=r"(a) : "l"(p));
    return a;
}
__device__ __forceinline__ void ldsm_x4(uint32_t* r, uint32_t addr) {
    asm volatile("ldmatrix.sync.aligned.m8n8.x4.shared.b16 {%0,%1,%2,%3}, [%4];"
        : "=r"(r[0]), "=r"(r[1]), "=r"(r[2]), "=r"(r[3]) : "r"(addr));
}
__device__ __forceinline__ void mma16816(float* d, const uint32_t* a, const uint32_t* b) {
    asm volatile(
        "mma.sync.aligned.m16n8k16.row.col.f32.bf16.bf16.f32 "
        "{%0,%1,%2,%3}, {%4,%5,%6,%7}, {%8,%9}, {%0,%1,%2,%3};"
        : "+f"(d[0]), "+f"(d[1]), "+f"(d[2]), "+f"(d[3])
        : "r"(a[0]), "r"(a[1]), "r"(a[2]), "r"(a[3]), "r"(b[0]), "r"(b[1]));
}
#define CP_ASYNC16(dst_u32, src_ptr) \
    asm volatile("cp.async.cg.shared.global [%0], [%1], 16;" :: "r"(dst_u32), "l"(src_ptr))
#define CP_COMMIT() asm volatile("cp.async.commit_group;")
#define CP_WAIT0()  asm volatile("cp.async.wait_group 0;")

__device__ __forceinline__ uint32_t packbf(float a, float b) {
    __nv_bfloat16 ba = __float2bfloat16(a), bb = __float2bfloat16(b);
    return ((uint32_t)__bfloat16_as_ushort(bb) << 16) | __bfloat16_as_ushort(ba);
}
__device__ __forceinline__ void cvt8(const float* f, uint4& hv, uint4& lv) {
    unsigned h[4], l[4];
    #pragma unroll
    for (int j = 0; j < 4; j++) {
        __nv_bfloat16 a0 = __float2bfloat16(f[2*j]);
        __nv_bfloat16 a1 = __float2bfloat16(f[2*j+1]);
        __nv_bfloat16 b0 = __float2bfloat16(f[2*j]   - __bfloat162float(a0));
        __nv_bfloat16 b1 = __float2bfloat16(f[2*j+1] - __bfloat162float(a1));
        h[j] = ((unsigned)__bfloat16_as_ushort(a1) << 16) | __bfloat16_as_ushort(a0);
        l[j] = ((unsigned)__bfloat16_as_ushort(b1) << 16) | __bfloat16_as_ushort(b0);
    }
    hv = make_uint4(h[0], h[1], h[2], h[3]);
    lv = make_uint4(l[0], l[1], l[2], l[3]);
}

// ---------------- K1: weight images + histogram + (last block) chunk scan ----
__global__ void k1_init_hist(const float* __restrict__ W1, const float* __restrict__ W2,
                             const int* __restrict__ dst, int e, int n, int npart) {
    int i = blockIdx.x * 1024 + threadIdx.x;
    if (i < 32768) {                          // W1^T: n<256, k<128
        int nn = i >> 7, k = i & 127;
        float w = W1[k * 256 + nn];
        __nv_bfloat16 hi = __float2bfloat16(w);
        __nv_bfloat16 lo = __float2bfloat16(w - __bfloat162float(hi));
        int off = nn * 272 + k * 2;
        *(unsigned short*)(g_W1img_hi + off) = __bfloat16_as_ushort(hi);
        *(unsigned short*)(g_W1img_lo + off) = __bfloat16_as_ushort(lo);
    } else if (i < 65536) {                   // W2^T: n<128, k<256
        int j = i - 32768;
        int nn = j >> 8, k = j & 255;
        float w = W2[k * 128 + nn];
        __nv_bfloat16 hi = __float2bfloat16(w);
        __nv_bfloat16 lo = __float2bfloat16(w - __bfloat162float(hi));
        int off = (k >> 7) * 34816 + nn * 272 + (k & 127) * 2;
        *(unsigned short*)(g_W2img_hi + off) = __bfloat16_as_ushort(hi);
        *(unsigned short*)(g_W2img_lo + off) = __bfloat16_as_ushort(lo);
    }
    if (i < e) atomicAdd(&g_deg[dst[i]], 1);

    // last block performs per-chunk sums + scan of chunk totals
    __threadfence();
    __shared__ int s_last;
    if (threadIdx.x == 0) s_last = (atomicAdd(&g_done1, 1) == (int)gridDim.x - 1);
    __syncthreads();
    if (!s_last) return;
    if (threadIdx.x == 0) g_done1 = 0;

    __shared__ int csum[NPARTMAX];
    __shared__ int sh[NPARTMAX];
    int t = threadIdx.x, lane = t & 31, w = t >> 5;
    for (int c = w; c < npart; c += 32) {
        int s = 0;
        for (int k = lane; k < 1024; k += 32) {
            int idx = (c << 10) + k;
            s += (idx < n) ? g_deg[idx] : 0;
        }
        #pragma unroll
        for (int o = 16; o > 0; o >>= 1) s += __shfl_xor_sync(0xffffffffu, s, o);
        if (lane == 0) csum[c] = s;
    }
    __syncthreads();
    if (t < NPARTMAX) sh[t] = (t < npart) ? csum[t] : 0;
    __syncthreads();
    for (int o = 1; o < NPARTMAX; o <<= 1) {
        int add = (t < NPARTMAX && t >= o) ? sh[t - o] : 0;
        __syncthreads();
        if (t < NPARTMAX) sh[t] += add;
        __syncthreads();
    }
    if (t < npart) g_partoffs[t] = sh[t] - csum[t];
    if (t == npart - 1) g_offs[n] = sh[t];
}

// ---------------- local scan within each 1024-chunk (+ g_deg reset) ----------
__global__ void scan_local_kernel(int n) {
    __shared__ int warpsums[32];
    int t = threadIdx.x, lane = t & 31, w = t >> 5;
    int i = blockIdx.x * 1024 + t;
    int v = (i < n) ? g_deg[i] : 0;
    int s = v;
    #pragma unroll
    for (int o = 1; o < 32; o <<= 1) {
        int u = __shfl_up_sync(0xffffffffu, s, o);
        if (lane >= o) s += u;
    }
    if (lane == 31) warpsums[w] = s;
    __syncthreads();
    if (w == 0) {
        int ws = warpsums[lane];
        #pragma unroll
        for (int o = 1; o < 32; o <<= 1) {
            int u = __shfl_up_sync(0xffffffffu, ws, o);
            if (lane >= o) ws += u;
        }
        warpsums[lane] = ws;
    }
    __syncthreads();
    if (i < n) {
        int ex = g_partoffs[blockIdx.x] + s - v + (w > 0 ? warpsums[w - 1] : 0);
        g_offs[i] = ex;
        g_cur[i] = ex;
        g_deg[i] = 0;   // restore invariant for next launch/replay
    }
}

__global__ void scatter_kernel(const int* __restrict__ src, const int* __restrict__ dst, int e) {
    int i = blockIdx.x * blockDim.x + threadIdx.x;
    if (i < e) {
        int pos = atomicAdd(&g_cur[dst[i]], 1);
        g_srcs[pos] = src[i];
    }
}

// ---------------- GEMM1 (persistent, fused agg + mma + BN stats/finalize) ----
#define G1_AHI  0
#define G1_ALO  34816
#define G1_BHI  69632
#define G1_BLO  139264
#define G1_BIAS 208896
#define G1_SMEM 209920

__global__ __launch_bounds__(256) void gemm1_mma(const float* __restrict__ x,
                                                 const float* __restrict__ t_ptr,
                                                 const float* __restrict__ b1,
                                                 const float* __restrict__ bn_gamma,
                                                 const float* __restrict__ bn_beta,
                                                 int M, int nb) {
    extern __shared__ char smem[];
    uint32_t sb = smem_u32(smem);
    int tid = threadIdx.x, w = tid >> 5, lane = tid & 31;
    float* b1s = (float*)(smem + G1_BIAS);
    b1s[tid] = __ldg(&b1[tid]);
    float t = *t_ptr;

    // B tiles via cp.async, loaded ONCE per CTA
    for (int u = tid; u < 4352; u += 256) {
        CP_ASYNC16(sb + G1_BHI + u * 16, (const char*)g_W1img_hi + u * 16);
        CP_ASYNC16(sb + G1_BLO + u * 16, (const char*)g_W1img_lo + u * 16);
    }
    CP_COMMIT();

    int m0 = (w & 1) * 64, n0 = (w >> 1) * 64;
    int lr = lane & 7, mid = lane >> 3;
    uint32_t aoff = (uint32_t)((m0 + lr + ((mid & 1) << 3)) * 272 + ((mid >> 1) << 4));
    uint32_t boff = (uint32_t)((n0 + lr + ((mid >> 1) << 3)) * 272 + ((mid & 1) << 4));
    uint32_t aHb = sb + G1_AHI + aoff, aLb = sb + G1_ALO + aoff;
    uint32_t bHb = sb + G1_BHI + boff, bLb = sb + G1_BLO + boff;

    for (int rb = blockIdx.x; rb < nb; rb += gridDim.x) {
        int row0 = rb * 128;
        __syncthreads();   // protect A buffer from previous iteration's ldmatrix

        // fused softmax aggregation -> A tile (warp w owns rows w*16..w*16+15)
        for (int mr = 0; mr < 16; mr++) {
            int m = (w << 4) + mr;
            int node = row0 + m;
            float hx = 0.f, hy = 0.f, hz = 0.f, hw = 0.f;
            if (node < M) {
                int beg = g_offs[node], end = g_offs[node + 1];
                float s0 = 0.f, s1 = 0.f, s2 = 0.f, s3 = 0.f;
                float d0 = 0.f, d1 = 0.f, d2 = 0.f, d3 = 0.f;
                int e = beg;
                while (e < end) {
                    int cnt = end - e; if (cnt > 4) cnt = 4;
                    float4 qa[4];
                    #pragma unroll
                    for (int j = 0; j < 4; j++)
                        if (j < cnt)
                            qa[j] = __ldg((const float4*)(x + (size_t)__ldg(&g_srcs[e + j]) * D) + lane);
                    #pragma unroll
                    for (int j = 0; j < 4; j++) {
                        if (j < cnt) {
                            float v0 = fmaxf(qa[j].x, 0.f) + MSG_EPS;
                            float v1 = fmaxf(qa[j].y, 0.f) + MSG_EPS;
                            float v2 = fmaxf(qa[j].z, 0.f) + MSG_EPS;
                            float v3 = fmaxf(qa[j].w, 0.f) + MSG_EPS;
                            float e0 = __expf(t * v0), e1 = __expf(t * v1);
                            float e2 = __expf(t * v2), e3 = __expf(t * v3);
                            d0 += e0; d1 += e1; d2 += e2; d3 += e3;
                            s0 += e0 * v0; s1 += e1 * v1; s2 += e2 * v2; s3 += e3 * v3;
                        }
                    }
                    e += cnt;
                }
                float4 xq = __ldg((const float4*)(x + (size_t)node * D) + lane);
                hx = s0 / (d0 + SM_EPS) + xq.x;
                hy = s1 / (d1 + SM_EPS) + xq.y;
                hz = s2 / (d2 + SM_EPS) + xq.z;
                hw = s3 / (d3 + SM_EPS) + xq.w;
            }
            uint32_t hi0 = packbf(hx, hy), hi1 = packbf(hz, hw);
            float rx = hx - __bfloat162float(__float2bfloat16(hx));
            float ry = hy - __bfloat162float(__float2bfloat16(hy));
            float rz = hz - __bfloat162float(__float2bfloat16(hz));
            float rw = hw - __bfloat162float(__float2bfloat16(hw));
            uint32_t lo0 = packbf(rx, ry), lo1 = packbf(rz, rw);
            int off = m * 272 + lane * 8;
            *(uint2*)(smem + G1_AHI + off) = make_uint2(hi0, hi1);
            *(uint2*)(smem + G1_ALO + off) = make_uint2(lo0, lo1);
        }
        CP_WAIT0();
        __syncthreads();

        float acc[4][8][4];
        #pragma unroll
        for (int i = 0; i < 4; i++)
            #pragma unroll
            for (int j = 0; j < 8; j++)
                #pragma unroll
                for (int q = 0; q < 4; q++) acc[i][j][q] = 0.f;

        #pragma unroll
        for (int ks = 0; ks < 8; ks++) {
            uint32_t kb = ks << 5;
            uint32_t aH[4][4], aL[4][4];
            #pragma unroll
            for (int mb = 0; mb < 4; mb++) {
                ldsm_x4(aH[mb], aHb + mb * 4352 + kb);
                ldsm_x4(aL[mb], aLb + mb * 4352 + kb);
            }
            #pragma unroll
            for (int nbp = 0; nbp < 4; nbp++) {
                uint32_t bh[4], bl[4];
                ldsm_x4(bh, bHb + nbp * 4352 + kb);
                ldsm_x4(bl, bLb + nbp * 4352 + kb);
                #pragma unroll
                for (int mb = 0; mb < 4; mb++) {
                    mma16816(acc[mb][2*nbp],     aH[mb], bh);
                    mma16816(acc[mb][2*nbp],     aH[mb], bl);
                    mma16816(acc[mb][2*nbp],     aL[mb], bh);
                    mma16816(acc[mb][2*nbp + 1], aH[mb], bh + 2);
                    mma16816(acc[mb][2*nbp + 1], aH[mb], bl + 2);
                    mma16816(acc[mb][2*nbp + 1], aL[mb], bh + 2);
                }
            }
        }

        // epilogue: + bias, store h1, column partials -> global atomics
        int mtop = row0 + m0 + (lane >> 2);
        int nc = n0 + 2 * (lane & 3);
        float cs[8][2], cq[8][2];
        #pragma unroll
        for (int j = 0; j < 8; j++) { cs[j][0] = cs[j][1] = cq[j][0] = cq[j][1] = 0.f; }
        #pragma unroll
        for (int mb = 0; mb < 4; mb++) {
            int r0 = mtop + mb * 16;
            bool gd0 = r0 < M, gd1 = (r0 + 8) < M;
            #pragma unroll
            for (int nbq = 0; nbq < 8; nbq++) {
                int n = nc + nbq * 8;
                float bv0 = b1s[n], bv1 = b1s[n + 1];
                float o0 = acc[mb][nbq][0] + bv0, o1 = acc[mb][nbq][1] + bv1;
                float o2 = acc[mb][nbq][2] + bv0, o3 = acc[mb][nbq][3] + bv1;
                size_t r1 = (size_t)r0 * 256 + n;
                *(float2*)(g_h1 + r1)           = make_float2(o0, o1);
                *(float2*)(g_h1 + r1 + 8 * 256) = make_float2(o2, o3);
                cs[nbq][0] += (gd0 ? o0 : 0.f) + (gd1 ? o2 : 0.f);
                cs[nbq][1] += (gd0 ? o1 : 0.f) + (gd1 ? o3 : 0.f);
                cq[nbq][0] += (gd0 ? o0 * o0 : 0.f) + (gd1 ? o2 * o2 : 0.f);
                cq[nbq][1] += (gd0 ? o1 * o1 : 0.f) + (gd1 ? o3 * o3 : 0.f);
            }
        }
        #pragma unroll
        for (int nbq = 0; nbq < 8; nbq++) {
            #pragma unroll
            for (int o = 16; o >= 4; o >>= 1) {
                cs[nbq][0] += __shfl_down_sync(0xffffffffu, cs[nbq][0], o);
                cs[nbq][1] += __shfl_down_sync(0xffffffffu, cs[nbq][1], o);
                cq[nbq][0] += __shfl_down_sync(0xffffffffu, cq[nbq][0], o);
                cq[nbq][1] += __shfl_down_sync(0xffffffffu, cq[nbq][1], o);
            }
        }
        if (lane < 4) {
            #pragma unroll
            for (int nbq = 0; nbq < 8; nbq++) {
                int ncol = n0 + nbq * 8 + 2 * lane;
                atomicAdd(&g_colsum[ncol],     cs[nbq][0]);
                atomicAdd(&g_colsum[ncol + 1], cs[nbq][1]);
                atomicAdd(&g_colsq[ncol],      cq[nbq][0]);
                atomicAdd(&g_colsq[ncol + 1],  cq[nbq][1]);
            }
        }
    }

    // last CTA finalizes BN scale/shift and resets accumulators
    __threadfence();
    __shared__ int s_last;
    if (tid == 0) s_last = (atomicAdd(&g_done2, 1) == (int)gridDim.x - 1);
    __syncthreads();
    if (s_last) {
        float inv_n = 1.f / (float)M;
        float mu  = g_colsum[tid] * inv_n;
        float var = g_colsq[tid] * inv_n - mu * mu;
        float sc  = __ldg(&bn_gamma[tid]) * rsqrtf(var + BN_EPS);
        g_bnscale[tid] = sc;
        g_bnshift[tid] = __ldg(&bn_beta[tid]) - mu * sc;
        g_colsum[tid] = 0.f;
        g_colsq[tid]  = 0.f;
        if (tid == 0) g_done2 = 0;
    }
}

// ---------------- GEMM2 (persistent): out = x + relu(LN(relu(BN(h1))@W2+b2)) -
#define G2_AHI   0
#define G2_ALO   34816
#define G2_B     69632      /* phase p: BHI = G2_B + p*69632, BLO = +34816 */
#define G2_CST   0
#define G2_CONST 208896     /* sc256|sh256|b2 128|lg 128|lb 128 = 3584 */
#define G2_SMEM  212480

__global__ __launch_bounds__(256) void gemm2_mma(const float* __restrict__ b2,
                                                 const float* __restrict__ ln_gamma,
                                                 const float* __restrict__ ln_beta,
                                                 const float* __restrict__ x,
                                                 float* __restrict__ out, int M, int nb) {
    extern __shared__ char smem[];
    uint32_t sb = smem_u32(smem);
    int tid = threadIdx.x, w = tid >> 5, lane = tid & 31;

    float* s_sc = (float*)(smem + G2_CONST);
    float* s_sh = s_sc + 256;
    float* s_b2 = s_sh + 256;
    float* s_lg = s_b2 + 128;
    float* s_lb = s_lg + 128;
    s_sc[tid] = g_bnscale[tid];
    s_sh[tid] = g_bnshift[tid];
    if (tid < 128) {
        s_b2[tid] = __ldg(&b2[tid]);
        s_lg[tid] = __ldg(&ln_gamma[tid]);
        s_lb[tid] = __ldg(&ln_beta[tid]);
    }
    for (int u = tid; u < 2176; u += 256) {
        #pragma unroll
        for (int p = 0; p < 2; p++) {
            CP_ASYNC16(sb + G2_B + p * 69632 + u * 16,         (const char*)g_W2img_hi + p * 34816 + u * 16);
            CP_ASYNC16(sb + G2_B + p * 69632 + 34816 + u * 16, (const char*)g_W2img_lo + p * 34816 + u * 16);
        }
    }
    CP_COMMIT();

    int m0 = (w & 1) * 64, n0 = (w >> 1) * 32;
    int lr = lane & 7, mid = lane >> 3;
    uint32_t aoff = (uint32_t)((m0 + lr + ((mid & 1) << 3)) * 272 + ((mid >> 1) << 4));
    uint32_t boff = (uint32_t)((n0 + lr + ((mid >> 1) << 3)) * 272 + ((mid & 1) << 4));
    uint32_t aHb = sb + G2_AHI + aoff, aLb = sb + G2_ALO + aoff;

    for (int rb = blockIdx.x; rb < nb; rb += gridDim.x) {
        int row0 = rb * 128;
        float acc[4][4][4];
        #pragma unroll
        for (int i = 0; i < 4; i++)
            #pragma unroll
            for (int j = 0; j < 4; j++)
                #pragma unroll
                for (int q = 0; q < 4; q++) acc[i][j][q] = 0.f;

        for (int p = 0; p < 2; p++) {
            __syncthreads();
            for (int u = tid; u < 2048; u += 256) {
                int m = u >> 4, g = u & 15;
                int kc = (p << 7) + (g << 3);
                const float4* hr = (const float4*)(g_h1 + (size_t)(row0 + m) * 256 + kc);
                float4 q0 = hr[0], q1 = hr[1];
                float f[8] = {q0.x, q0.y, q0.z, q0.w, q1.x, q1.y, q1.z, q1.w};
                #pragma unroll
                for (int j = 0; j < 8; j++)
                    f[j] = fmaxf(fmaf(f[j], s_sc[kc + j], s_sh[kc + j]), 0.f);
                uint4 hv, lv; cvt8(f, hv, lv);
                int off = m * 272 + g * 16;
                *(uint4*)(smem + G2_AHI + off) = hv;
                *(uint4*)(smem + G2_ALO + off) = lv;
            }
            CP_WAIT0();
            __syncthreads();

            uint32_t bHb = sb + G2_B + p * 69632 + boff;
            uint32_t bLb = bHb + 34816;
            #pragma unroll
            for (int ks = 0; ks < 8; ks++) {
                uint32_t kb = ks << 5;
                uint32_t aH[4][4], aL[4][4];
                #pragma unroll
                for (int mb = 0; mb < 4; mb++) {
                    ldsm_x4(aH[mb], aHb + mb * 4352 + kb);
                    ldsm_x4(aL[mb], aLb + mb * 4352 + kb);
                }
                #pragma unroll
                for (int nbp = 0; nbp < 2; nbp++) {
                    uint32_t bh[4], bl[4];
                    ldsm_x4(bh, bHb + nbp * 4352 + kb);
                    ldsm_x4(bl, bLb + nbp * 4352 + kb);
                    #pragma unroll
                    for (int mb = 0; mb < 4; mb++) {
                        mma16816(acc[mb][2*nbp],     aH[mb], bh);
                        mma16816(acc[mb][2*nbp],     aH[mb], bl);
                        mma16816(acc[mb][2*nbp],     aL[mb], bh);
                        mma16816(acc[mb][2*nbp + 1], aH[mb], bh + 2);
                        mma16816(acc[mb][2*nbp + 1], aH[mb], bl + 2);
                        mma16816(acc[mb][2*nbp + 1], aL[mb], bh + 2);
                    }
                }
            }
        }
        __syncthreads();

        float* Cs = (float*)(smem + G2_CST);
        {
            int mtop = m0 + (lane >> 2), nc = n0 + 2 * (lane & 3);
            #pragma unroll
            for (int mb = 0; mb < 4; mb++) {
                #pragma unroll
                for (int nbq = 0; nbq < 4; nbq++) {
                    int n = nc + nbq * 8;
                    int rr = mtop + mb * 16;
                    *(float2*)(Cs + rr * 132 + n)       = make_float2(acc[mb][nbq][0], acc[mb][nbq][1]);
                    *(float2*)(Cs + (rr + 8) * 132 + n) = make_float2(acc[mb][nbq][2], acc[mb][nbq][3]);
                }
            }
        }
        __syncthreads();

        if (tid < 128) {
            int grow = row0 + tid;
            const float* cr = Cs + tid * 132;
            float sum = 0.f, sq = 0.f;
            #pragma unroll
            for (int c = 0; c < 128; c += 4) {
                float4 q = *(const float4*)(cr + c);
                float v0 = q.x + s_b2[c], v1 = q.y + s_b2[c+1];
                float v2 = q.z + s_b2[c+2], v3 = q.w + s_b2[c+3];
                sum += v0 + v1 + v2 + v3;
                sq  += v0*v0 + v1*v1 + v2*v2 + v3*v3;
            }
            float mu = sum * (1.f / D);
            float var = sq * (1.f / D) - mu * mu;
            float rr = rsqrtf(var + LN_EPS);
            if (grow < M) {
                const float4* xr = (const float4*)(x + (size_t)grow * D);
                float4* po = (float4*)(out + (size_t)grow * D);
                #pragma unroll
                for (int c = 0; c < 128; c += 4) {
                    float4 q = *(const float4*)(cr + c);
                    float4 xv = __ldg(xr + (c >> 2));
                    float4 o;
                    o.x = xv.x + fmaxf((q.x + s_b2[c]   - mu) * rr * s_lg[c]   + s_lb[c],   0.f);
                    o.y = xv.y + fmaxf((q.y + s_b2[c+1] - mu) * rr * s_lg[c+1] + s_lb[c+1], 0.f);
                    o.z = xv.z + fmaxf((q.z + s_b2[c+2] - mu) * rr * s_lg[c+2] + s_lb[c+2], 0.f);
                    o.w = xv.w + fmaxf((q.w + s_b2[c+3] - mu) * rr * s_lg[c+3] + s_lb[c+3], 0.f);
                    po[c >> 2] = o;
                }
            }
        }
    }
}

// ---------------- launcher ---------------------------------------------------
extern "C" void kernel_launch(void* const* d_in, const int* in_sizes, int n_in,
                              void* d_out, int out_size) {
    const float* x        = (const float*)d_in[0];
    const int*   ei       = (const int*)  d_in[1];
    const float* t_ptr    = (const float*)d_in[2];
    const float* W1       = (const float*)d_in[3];
    const float* b1       = (const float*)d_in[4];
    const float* bn_gamma = (const float*)d_in[5];
    const float* bn_beta  = (const float*)d_in[6];
    const float* W2       = (const float*)d_in[7];
    const float* b2       = (const float*)d_in[8];
    const float* ln_gamma = (const float*)d_in[9];
    const float* ln_beta  = (const float*)d_in[10];
    float* out = (float*)d_out;

    int n = in_sizes[0] / D;
    int e = in_sizes[1] / 2;
    const int* src = ei;
    const int* dst = ei + e;
    int nb = (n + 127) / 128;
    int npart = (n + 1023) / 1024;
    int gpers = nb < 152 ? nb : 152;
    int hb = ((e > 65536 ? e : 65536) + 1023) / 1024;

    cudaFuncSetAttribute(gemm1_mma, cudaFuncAttributeMaxDynamicSharedMemorySize, G1_SMEM);
    cudaFuncSetAttribute(gemm2_mma, cudaFuncAttributeMaxDynamicSharedMemorySize, G2_SMEM);

    k1_init_hist<<<hb, 1024>>>(W1, W2, dst, e, n, npart);
    scan_local_kernel<<<npart, 1024>>>(n);
    scatter_kernel<<<(e + 255) / 256, 256>>>(src, dst, e);
    gemm1_mma<<<gpers, 256, G1_SMEM>>>(x, t_ptr, b1, bn_gamma, bn_beta, n, nb);
    gemm2_mma<<<gpers, 256, G2_SMEM>>>(b2, ln_gamma, ln_beta, x, out, n, nb);
}

// round 11
// speedup vs baseline: 1.4844x; 1.4844x over previous
#include <cuda_runtime.h>
#include <cuda_bf16.h>
#include <math_constants.h>
#include <cstdint>

#define NMAX 50176
#define EMAX 800000
#define D    128
#define D2   256
#define MSG_EPS 1e-7f
#define SM_EPS  1e-16f
#define BN_EPS  1e-5f
#define LN_EPS  1e-5f
#define NPARTMAX 64
#define NBMAX 392

// ---------------- scratch (static device globals; no allocation) -------------
__device__ int   g_deg[NMAX];          // zero at entry (reset by scan_local)
__device__ int   g_offs[NMAX + 1];
__device__ int   g_cur[NMAX];
__device__ int   g_srcs[EMAX];
__device__ int   g_partoffs[NPARTMAX];
__device__ int   g_done1;              // reset by K1 last block
__device__ float g_h0[(size_t)NMAX * D];
__device__ float g_h1[(size_t)NMAX * D2];
__device__ float g_bnpart[(size_t)NBMAX * 512];
__device__ float g_bnscale[D2];
__device__ float g_bnshift[D2];
__device__ __align__(16) unsigned char g_W1img_hi[69632];
__device__ __align__(16) unsigned char g_W1img_lo[69632];
__device__ __align__(16) unsigned char g_W2img_hi[69632];
__device__ __align__(16) unsigned char g_W2img_lo[69632];

// ---------------- helpers ----------------------------------------------------
__device__ __forceinline__ uint32_t smem_u32(const void* p) {
    uint32_t a;
    asm("{ .reg .u64 t; cvta.to.shared.u64 t, %1; cvt.u32.u64 %0, t; }" : "=r"(a) : "l"(p));
    return a;
}
__device__ __forceinline__ void ldsm_x4(uint32_t* r, uint32_t addr) {
    asm volatile("ldmatrix.sync.aligned.m8n8.x4.shared.b16 {%0,%1,%2,%3}, [%4];"
        : "=r"(r[0]), "=r"(r[1]), "=r"(r[2]), "=r"(r[3]) : "r"(addr));
}
__device__ __forceinline__ void mma16816(float* d, const uint32_t* a, const uint32_t* b) {
    asm volatile(
        "mma.sync.aligned.m16n8k16.row.col.f32.bf16.bf16.f32 "
        "{%0,%1,%2,%3}, {%4,%5,%6,%7}, {%8,%9}, {%0,%1,%2,%3};"
        : "+f"(d[0]), "+f"(d[1]), "+f"(d[2]), "+f"(d[3])
        : "r"(a[0]), "r"(a[1]), "r"(a[2]), "r"(a[3]), "r"(b[0]), "r"(b[1]));
}
#define CP_ASYNC16(dst_u32, src_ptr) \
    asm volatile("cp.async.cg.shared.global [%0], [%1], 16;" :: "r"(dst_u32), "l"(src_ptr))
#define CP_COMMIT() asm volatile("cp.async.commit_group;")
#define CP_WAIT0()  asm volatile("cp.async.wait_group 0;")

__device__ __forceinline__ void cvt8(const float* f, uint4& hv, uint4& lv) {
    unsigned h[4], l[4];
    #pragma unroll
    for (int j = 0; j < 4; j++) {
        __nv_bfloat16 a0 = __float2bfloat16(f[2*j]);
        __nv_bfloat16 a1 = __float2bfloat16(f[2*j+1]);
        __nv_bfloat16 b0 = __float2bfloat16(f[2*j]   - __bfloat162float(a0));
        __nv_bfloat16 b1 = __float2bfloat16(f[2*j+1] - __bfloat162float(a1));
        h[j] = ((unsigned)__bfloat16_as_ushort(a1) << 16) | __bfloat16_as_ushort(a0);
        l[j] = ((unsigned)__bfloat16_as_ushort(b1) << 16) | __bfloat16_as_ushort(b0);
    }
    hv = make_uint4(h[0], h[1], h[2], h[3]);
    lv = make_uint4(l[0], l[1], l[2], l[3]);
}

// ---------------- K1: weight images + histogram + (last block) chunk scan ----
__global__ void k1_init_hist(const float* __restrict__ W1, const float* __restrict__ W2,
                             const int* __restrict__ dst, int e, int n, int npart) {
    int i = blockIdx.x * 1024 + threadIdx.x;
    if (i < 32768) {                          // W1^T: n<256, k<128
        int nn = i >> 7, k = i & 127;
        float w = W1[k * 256 + nn];
        __nv_bfloat16 hi = __float2bfloat16(w);
        __nv_bfloat16 lo = __float2bfloat16(w - __bfloat162float(hi));
        int off = nn * 272 + k * 2;
        *(unsigned short*)(g_W1img_hi + off) = __bfloat16_as_ushort(hi);
        *(unsigned short*)(g_W1img_lo + off) = __bfloat16_as_ushort(lo);
    } else if (i < 65536) {                   // W2^T: n<128, k<256
        int j = i - 32768;
        int nn = j >> 8, k = j & 255;
        float w = W2[k * 128 + nn];
        __nv_bfloat16 hi = __float2bfloat16(w);
        __nv_bfloat16 lo = __float2bfloat16(w - __bfloat162float(hi));
        int off = (k >> 7) * 34816 + nn * 272 + (k & 127) * 2;
        *(unsigned short*)(g_W2img_hi + off) = __bfloat16_as_ushort(hi);
        *(unsigned short*)(g_W2img_lo + off) = __bfloat16_as_ushort(lo);
    }
    if (i < e) atomicAdd(&g_deg[dst[i]], 1);

    __threadfence();
    __shared__ int s_last;
    if (threadIdx.x == 0) s_last = (atomicAdd(&g_done1, 1) == (int)gridDim.x - 1);
    __syncthreads();
    if (!s_last) return;
    if (threadIdx.x == 0) g_done1 = 0;

    __shared__ int csum[NPARTMAX];
    __shared__ int sh[NPARTMAX];
    int t = threadIdx.x, lane = t & 31, w = t >> 5;
    for (int c = w; c < npart; c += 32) {
        int s = 0;
        for (int k = lane; k < 1024; k += 32) {
            int idx = (c << 10) + k;
            s += (idx < n) ? g_deg[idx] : 0;
        }
        #pragma unroll
        for (int o = 16; o > 0; o >>= 1) s += __shfl_xor_sync(0xffffffffu, s, o);
        if (lane == 0) csum[c] = s;
    }
    __syncthreads();
    if (t < NPARTMAX) sh[t] = (t < npart) ? csum[t] : 0;
    __syncthreads();
    for (int o = 1; o < NPARTMAX; o <<= 1) {
        int add = (t < NPARTMAX && t >= o) ? sh[t - o] : 0;
        __syncthreads();
        if (t < NPARTMAX) sh[t] += add;
        __syncthreads();
    }
    if (t < npart) g_partoffs[t] = sh[t] - csum[t];
    if (t == npart - 1) g_offs[n] = sh[t];
}

// ---------------- local scan within each 1024-chunk (+ g_deg reset) ----------
__global__ void scan_local_kernel(int n) {
    __shared__ int warpsums[32];
    int t = threadIdx.x, lane = t & 31, w = t >> 5;
    int i = blockIdx.x * 1024 + t;
    int v = (i < n) ? g_deg[i] : 0;
    int s = v;
    #pragma unroll
    for (int o = 1; o < 32; o <<= 1) {
        int u = __shfl_up_sync(0xffffffffu, s, o);
        if (lane >= o) s += u;
    }
    if (lane == 31) warpsums[w] = s;
    __syncthreads();
    if (w == 0) {
        int ws = warpsums[lane];
        #pragma unroll
        for (int o = 1; o < 32; o <<= 1) {
            int u = __shfl_up_sync(0xffffffffu, ws, o);
            if (lane >= o) ws += u;
        }
        warpsums[lane] = ws;
    }
    __syncthreads();
    if (i < n) {
        int ex = g_partoffs[blockIdx.x] + s - v + (w > 0 ? warpsums[w - 1] : 0);
        g_offs[i] = ex;
        g_cur[i] = ex;
        g_deg[i] = 0;   // restore invariant for next replay
    }
}

__global__ void scatter_kernel(const int* __restrict__ src, const int* __restrict__ dst, int e) {
    int i = blockIdx.x * blockDim.x + threadIdx.x;
    if (i < e) {
        int pos = atomicAdd(&g_cur[dst[i]], 1);
        g_srcs[pos] = src[i];
    }
}

// ---------------- one-pass softmax aggregation (warp per node, MLP4) ---------
__global__ void agg_kernel(const float* __restrict__ x, const float* __restrict__ t_ptr, int n) {
    int gw   = (blockIdx.x * blockDim.x + threadIdx.x) >> 5;
    int lane = threadIdx.x & 31;
    if (gw >= n) return;
    float t = *t_ptr;
    int beg = g_offs[gw], end = g_offs[gw + 1];

    float n0 = 0.f, n1 = 0.f, n2 = 0.f, n3 = 0.f;
    float d0 = 0.f, d1 = 0.f, d2 = 0.f, d3 = 0.f;
    int e = beg;
    while (e < end) {
        int cnt = end - e; if (cnt > 4) cnt = 4;
        float4 qa[4];
        #pragma unroll
        for (int j = 0; j < 4; j++)
            if (j < cnt)
                qa[j] = __ldg((const float4*)(x + (size_t)__ldg(&g_srcs[e + j]) * D) + lane);
        #pragma unroll
        for (int j = 0; j < 4; j++) {
            if (j < cnt) {
                float v0 = fmaxf(qa[j].x, 0.f) + MSG_EPS;
                float v1 = fmaxf(qa[j].y, 0.f) + MSG_EPS;
                float v2 = fmaxf(qa[j].z, 0.f) + MSG_EPS;
                float v3 = fmaxf(qa[j].w, 0.f) + MSG_EPS;
                float e0 = __expf(t * v0), e1 = __expf(t * v1);
                float e2 = __expf(t * v2), e3 = __expf(t * v3);
                d0 += e0; d1 += e1; d2 += e2; d3 += e3;
                n0 += e0 * v0; n1 += e1 * v1; n2 += e2 * v2; n3 += e3 * v3;
            }
        }
        e += cnt;
    }
    float4 xq = ((const float4*)(x + (size_t)gw * D))[lane];
    float4 h;
    h.x = n0 / (d0 + SM_EPS) + xq.x;
    h.y = n1 / (d1 + SM_EPS) + xq.y;
    h.z = n2 / (d2 + SM_EPS) + xq.z;
    h.w = n3 / (d3 + SM_EPS) + xq.w;
    ((float4*)(g_h0 + (size_t)gw * D))[lane] = h;
}

// ---------------- GEMM1 (persistent, mma.sync bf16 3x): h1 = h0 @ W1 + b1 ----
#define G1_AHI  0
#define G1_ALO  34816
#define G1_BHI  69632
#define G1_BLO  139264
#define G1_BIAS 208896
#define G1_STAT 209920      /* s_sum[8][64] | s_sq[8][64] = 4KB */
#define G1_SMEM 214016

__global__ __launch_bounds__(256) void gemm1_mma(const float* __restrict__ b1, int M, int nb) {
    extern __shared__ char smem[];
    uint32_t sb = smem_u32(smem);
    int tid = threadIdx.x, w = tid >> 5, lane = tid & 31;
    float* b1s = (float*)(smem + G1_BIAS);
    b1s[tid] = __ldg(&b1[tid]);

    for (int u = tid; u < 4352; u += 256) {
        CP_ASYNC16(sb + G1_BHI + u * 16, (const char*)g_W1img_hi + u * 16);
        CP_ASYNC16(sb + G1_BLO + u * 16, (const char*)g_W1img_lo + u * 16);
    }
    CP_COMMIT();

    int m0 = (w & 1) * 64, n0 = (w >> 1) * 64;
    int lr = lane & 7, mid = lane >> 3;
    uint32_t aoff = (uint32_t)((m0 + lr + ((mid & 1) << 3)) * 272 + ((mid >> 1) << 4));
    uint32_t boff = (uint32_t)((n0 + lr + ((mid >> 1) << 3)) * 272 + ((mid & 1) << 4));
    uint32_t aHb = sb + G1_AHI + aoff, aLb = sb + G1_ALO + aoff;
    uint32_t bHb = sb + G1_BHI + boff, bLb = sb + G1_BLO + boff;
    float* s_sum = (float*)(smem + G1_STAT);
    float* s_sq  = s_sum + 512;

    for (int rb = blockIdx.x; rb < nb; rb += gridDim.x) {
        int row0 = rb * 128;
        __syncthreads();

        for (int u = tid; u < 2048; u += 256) {
            int m = u >> 4, g = u & 15;
            const float4* ar = (const float4*)(g_h0 + ((size_t)(row0 + m) << 7) + (g << 3));
            float4 q0 = ar[0], q1 = ar[1];
            float f[8] = {q0.x, q0.y, q0.z, q0.w, q1.x, q1.y, q1.z, q1.w};
            uint4 hv, lv; cvt8(f, hv, lv);
            int off = m * 272 + g * 16;
            *(uint4*)(smem + G1_AHI + off) = hv;
            *(uint4*)(smem + G1_ALO + off) = lv;
        }
        CP_WAIT0();
        __syncthreads();

        float acc[4][8][4];
        #pragma unroll
        for (int i = 0; i < 4; i++)
            #pragma unroll
            for (int j = 0; j < 8; j++)
                #pragma unroll
                for (int q = 0; q < 4; q++) acc[i][j][q] = 0.f;

        #pragma unroll
        for (int ks = 0; ks < 8; ks++) {
            uint32_t kb = ks << 5;
            uint32_t aH[4][4], aL[4][4];
            #pragma unroll
            for (int mb = 0; mb < 4; mb++) {
                ldsm_x4(aH[mb], aHb + mb * 4352 + kb);
                ldsm_x4(aL[mb], aLb + mb * 4352 + kb);
            }
            #pragma unroll
            for (int nbp = 0; nbp < 4; nbp++) {
                uint32_t bh[4], bl[4];
                ldsm_x4(bh, bHb + nbp * 4352 + kb);
                ldsm_x4(bl, bLb + nbp * 4352 + kb);
                #pragma unroll
                for (int mb = 0; mb < 4; mb++) {
                    mma16816(acc[mb][2*nbp],     aH[mb], bh);
                    mma16816(acc[mb][2*nbp],     aH[mb], bl);
                    mma16816(acc[mb][2*nbp],     aL[mb], bh);
                    mma16816(acc[mb][2*nbp + 1], aH[mb], bh + 2);
                    mma16816(acc[mb][2*nbp + 1], aH[mb], bl + 2);
                    mma16816(acc[mb][2*nbp + 1], aL[mb], bh + 2);
                }
            }
        }

        int mtop = row0 + m0 + (lane >> 2);
        int nc = n0 + 2 * (lane & 3);
        float cs[8][2], cq[8][2];
        #pragma unroll
        for (int j = 0; j < 8; j++) { cs[j][0] = cs[j][1] = cq[j][0] = cq[j][1] = 0.f; }
        #pragma unroll
        for (int mb = 0; mb < 4; mb++) {
            int r0 = mtop + mb * 16;
            bool gd0 = r0 < M, gd1 = (r0 + 8) < M;
            #pragma unroll
            for (int nbq = 0; nbq < 8; nbq++) {
                int n = nc + nbq * 8;
                float bv0 = b1s[n], bv1 = b1s[n + 1];
                float o0 = acc[mb][nbq][0] + bv0, o1 = acc[mb][nbq][1] + bv1;
                float o2 = acc[mb][nbq][2] + bv0, o3 = acc[mb][nbq][3] + bv1;
                size_t r1 = (size_t)r0 * 256 + n;
                *(float2*)(g_h1 + r1)           = make_float2(o0, o1);
                *(float2*)(g_h1 + r1 + 8 * 256) = make_float2(o2, o3);
                cs[nbq][0] += (gd0 ? o0 : 0.f) + (gd1 ? o2 : 0.f);
                cs[nbq][1] += (gd0 ? o1 : 0.f) + (gd1 ? o3 : 0.f);
                cq[nbq][0] += (gd0 ? o0 * o0 : 0.f) + (gd1 ? o2 * o2 : 0.f);
                cq[nbq][1] += (gd0 ? o1 * o1 : 0.f) + (gd1 ? o3 * o3 : 0.f);
            }
        }
        #pragma unroll
        for (int nbq = 0; nbq < 8; nbq++) {
            #pragma unroll
            for (int o = 16; o >= 4; o >>= 1) {
                cs[nbq][0] += __shfl_down_sync(0xffffffffu, cs[nbq][0], o);
                cs[nbq][1] += __shfl_down_sync(0xffffffffu, cs[nbq][1], o);
                cq[nbq][0] += __shfl_down_sync(0xffffffffu, cq[nbq][0], o);
                cq[nbq][1] += __shfl_down_sync(0xffffffffu, cq[nbq][1], o);
            }
        }
        if (lane < 4) {
            #pragma unroll
            for (int nbq = 0; nbq < 8; nbq++) {
                int cl = nbq * 8 + lane * 2;
                s_sum[w * 64 + cl]     = cs[nbq][0];
                s_sum[w * 64 + cl + 1] = cs[nbq][1];
                s_sq [w * 64 + cl]     = cq[nbq][0];
                s_sq [w * 64 + cl + 1] = cq[nbq][1];
            }
        }
        __syncthreads();
        {
            int col = tid;
            int g = col >> 6, cl = col & 63;
            float ssum = s_sum[(2 * g) * 64 + cl] + s_sum[(2 * g + 1) * 64 + cl];
            float ssq  = s_sq [(2 * g) * 64 + cl] + s_sq [(2 * g + 1) * 64 + cl];
            g_bnpart[(size_t)rb * 512 + col]       = ssum;
            g_bnpart[(size_t)rb * 512 + 256 + col] = ssq;
        }
    }
}

// ---------------- BN finalize ------------------------------------------------
__global__ void bnfinal_kernel(const float* __restrict__ gamma,
                               const float* __restrict__ beta, int n, int nblk) {
    __shared__ float sh[512];
    int t = threadIdx.x;      // 512
    float s = 0.f;
    for (int b = 0; b < nblk; b++) s += g_bnpart[(size_t)b * 512 + t];
    sh[t] = s;
    __syncthreads();
    if (t < D2) {
        float inv_n = 1.f / (float)n;
        float mu  = sh[t] * inv_n;
        float var = sh[t + 256] * inv_n - mu * mu;
        float sc  = gamma[t] * rsqrtf(var + BN_EPS);
        g_bnscale[t] = sc;
        g_bnshift[t] = beta[t] - mu * sc;
    }
}

// ---------------- GEMM2 (persistent): out = x + relu(LN(relu(BN(h1))@W2+b2)) -
#define G2_AHI   0
#define G2_ALO   34816
#define G2_B     69632
#define G2_CST   0
#define G2_CONST 208896
#define G2_SMEM  212480

__global__ __launch_bounds__(256) void gemm2_mma(const float* __restrict__ b2,
                                                 const float* __restrict__ ln_gamma,
                                                 const float* __restrict__ ln_beta,
                                                 const float* __restrict__ x,
                                                 float* __restrict__ out, int M, int nb) {
    extern __shared__ char smem[];
    uint32_t sb = smem_u32(smem);
    int tid = threadIdx.x, w = tid >> 5, lane = tid & 31;

    float* s_sc = (float*)(smem + G2_CONST);
    float* s_sh = s_sc + 256;
    float* s_b2 = s_sh + 256;
    float* s_lg = s_b2 + 128;
    float* s_lb = s_lg + 128;
    s_sc[tid] = g_bnscale[tid];
    s_sh[tid] = g_bnshift[tid];
    if (tid < 128) {
        s_b2[tid] = __ldg(&b2[tid]);
        s_lg[tid] = __ldg(&ln_gamma[tid]);
        s_lb[tid] = __ldg(&ln_beta[tid]);
    }
    for (int u = tid; u < 2176; u += 256) {
        #pragma unroll
        for (int p = 0; p < 2; p++) {
            CP_ASYNC16(sb + G2_B + p * 69632 + u * 16,         (const char*)g_W2img_hi + p * 34816 + u * 16);
            CP_ASYNC16(sb + G2_B + p * 69632 + 34816 + u * 16, (const char*)g_W2img_lo + p * 34816 + u * 16);
        }
    }
    CP_COMMIT();

    int m0 = (w & 1) * 64, n0 = (w >> 1) * 32;
    int lr = lane & 7, mid = lane >> 3;
    uint32_t aoff = (uint32_t)((m0 + lr + ((mid & 1) << 3)) * 272 + ((mid >> 1) << 4));
    uint32_t boff = (uint32_t)((n0 + lr + ((mid >> 1) << 3)) * 272 + ((mid & 1) << 4));
    uint32_t aHb = sb + G2_AHI + aoff, aLb = sb + G2_ALO + aoff;

    for (int rb = blockIdx.x; rb < nb; rb += gridDim.x) {
        int row0 = rb * 128;
        float acc[4][4][4];
        #pragma unroll
        for (int i = 0; i < 4; i++)
            #pragma unroll
            for (int j = 0; j < 4; j++)
                #pragma unroll
                for (int q = 0; q < 4; q++) acc[i][j][q] = 0.f;

        for (int p = 0; p < 2; p++) {
            __syncthreads();
            for (int u = tid; u < 2048; u += 256) {
                int m = u >> 4, g = u & 15;
                int kc = (p << 7) + (g << 3);
                const float4* hr = (const float4*)(g_h1 + (size_t)(row0 + m) * 256 + kc);
                float4 q0 = hr[0], q1 = hr[1];
                float f[8] = {q0.x, q0.y, q0.z, q0.w, q1.x, q1.y, q1.z, q1.w};
                #pragma unroll
                for (int j = 0; j < 8; j++)
                    f[j] = fmaxf(fmaf(f[j], s_sc[kc + j], s_sh[kc + j]), 0.f);
                uint4 hv, lv; cvt8(f, hv, lv);
                int off = m * 272 + g * 16;
                *(uint4*)(smem + G2_AHI + off) = hv;
                *(uint4*)(smem + G2_ALO + off) = lv;
            }
            CP_WAIT0();
            __syncthreads();

            uint32_t bHb = sb + G2_B + p * 69632 + boff;
            uint32_t bLb = bHb + 34816;
            #pragma unroll
            for (int ks = 0; ks < 8; ks++) {
                uint32_t kb = ks << 5;
                uint32_t aH[4][4], aL[4][4];
                #pragma unroll
                for (int mb = 0; mb < 4; mb++) {
                    ldsm_x4(aH[mb], aHb + mb * 4352 + kb);
                    ldsm_x4(aL[mb], aLb + mb * 4352 + kb);
                }
                #pragma unroll
                for (int nbp = 0; nbp < 2; nbp++) {
                    uint32_t bh[4], bl[4];
                    ldsm_x4(bh, bHb + nbp * 4352 + kb);
                    ldsm_x4(bl, bLb + nbp * 4352 + kb);
                    #pragma unroll
                    for (int mb = 0; mb < 4; mb++) {
                        mma16816(acc[mb][2*nbp],     aH[mb], bh);
                        mma16816(acc[mb][2*nbp],     aH[mb], bl);
                        mma16816(acc[mb][2*nbp],     aL[mb], bh);
                        mma16816(acc[mb][2*nbp + 1], aH[mb], bh + 2);
                        mma16816(acc[mb][2*nbp + 1], aH[mb], bl + 2);
                        mma16816(acc[mb][2*nbp + 1], aL[mb], bh + 2);
                    }
                }
            }
        }
        __syncthreads();

        float* Cs = (float*)(smem + G2_CST);
        {
            int mtop = m0 + (lane >> 2), nc = n0 + 2 * (lane & 3);
            #pragma unroll
            for (int mb = 0; mb < 4; mb++) {
                #pragma unroll
                for (int nbq = 0; nbq < 4; nbq++) {
                    int n = nc + nbq * 8;
                    int rr = mtop + mb * 16;
                    *(float2*)(Cs + rr * 132 + n)       = make_float2(acc[mb][nbq][0], acc[mb][nbq][1]);
                    *(float2*)(Cs + (rr + 8) * 132 + n) = make_float2(acc[mb][nbq][2], acc[mb][nbq][3]);
                }
            }
        }
        __syncthreads();

        if (tid < 128) {
            int grow = row0 + tid;
            const float* cr = Cs + tid * 132;
            float sum = 0.f, sq = 0.f;
            #pragma unroll
            for (int c = 0; c < 128; c += 4) {
                float4 q = *(const float4*)(cr + c);
                float v0 = q.x + s_b2[c], v1 = q.y + s_b2[c+1];
                float v2 = q.z + s_b2[c+2], v3 = q.w + s_b2[c+3];
                sum += v0 + v1 + v2 + v3;
                sq  += v0*v0 + v1*v1 + v2*v2 + v3*v3;
            }
            float mu = sum * (1.f / D);
            float var = sq * (1.f / D) - mu * mu;
            float rr = rsqrtf(var + LN_EPS);
            if (grow < M) {
                const float4* xr = (const float4*)(x + (size_t)grow * D);
                float4* po = (float4*)(out + (size_t)grow * D);
                #pragma unroll
                for (int c = 0; c < 128; c += 4) {
                    float4 q = *(const float4*)(cr + c);
                    float4 xv = __ldg(xr + (c >> 2));
                    float4 o;
                    o.x = xv.x + fmaxf((q.x + s_b2[c]   - mu) * rr * s_lg[c]   + s_lb[c],   0.f);
                    o.y = xv.y + fmaxf((q.y + s_b2[c+1] - mu) * rr * s_lg[c+1] + s_lb[c+1], 0.f);
                    o.z = xv.z + fmaxf((q.z + s_b2[c+2] - mu) * rr * s_lg[c+2] + s_lb[c+2], 0.f);
                    o.w = xv.w + fmaxf((q.w + s_b2[c+3] - mu) * rr * s_lg[c+3] + s_lb[c+3], 0.f);
                    po[c >> 2] = o;
                }
            }
        }
    }
}

// ---------------- launcher ---------------------------------------------------
extern "C" void kernel_launch(void* const* d_in, const int* in_sizes, int n_in,
                              void* d_out, int out_size) {
    const float* x        = (const float*)d_in[0];
    const int*   ei       = (const int*)  d_in[1];
    const float* t_ptr    = (const float*)d_in[2];
    const float* W1       = (const float*)d_in[3];
    const float* b1       = (const float*)d_in[4];
    const float* bn_gamma = (const float*)d_in[5];
    const float* bn_beta  = (const float*)d_in[6];
    const float* W2       = (const float*)d_in[7];
    const float* b2       = (const float*)d_in[8];
    const float* ln_gamma = (const float*)d_in[9];
    const float* ln_beta  = (const float*)d_in[10];
    float* out = (float*)d_out;

    int n = in_sizes[0] / D;
    int e = in_sizes[1] / 2;
    const int* src = ei;
    const int* dst = ei + e;
    int nb = (n + 127) / 128;
    int npart = (n + 1023) / 1024;
    int gpers = nb < 152 ? nb : 152;
    int hb = ((e > 65536 ? e : 65536) + 1023) / 1024;

    cudaFuncSetAttribute(gemm1_mma, cudaFuncAttributeMaxDynamicSharedMemorySize, G1_SMEM);
    cudaFuncSetAttribute(gemm2_mma, cudaFuncAttributeMaxDynamicSharedMemorySize, G2_SMEM);

    k1_init_hist<<<hb, 1024>>>(W1, W2, dst, e, n, npart);
    scan_local_kernel<<<npart, 1024>>>(n);
    scatter_kernel<<<(e + 255) / 256, 256>>>(src, dst, e);
    agg_kernel<<<(n * 32 + 255) / 256, 256>>>(x, t_ptr, n);
    gemm1_mma<<<gpers, 256, G1_SMEM>>>(b1, n, nb);
    bnfinal_kernel<<<1, 512>>>(bn_gamma, bn_beta, n, nb);
    gemm2_mma<<<gpers, 256, G2_SMEM>>>(b2, ln_gamma, ln_beta, x, out, n, nb);
}

// round 12
// speedup vs baseline: 1.6041x; 1.0806x over previous
#include <cuda_runtime.h>
#include <cuda_bf16.h>
#include <math_constants.h>
#include <cstdint>

#define NMAX 50176
#define EMAX 800000
#define D    128
#define D2   256
#define MSG_EPS 1e-7f
#define SM_EPS  1e-16f
#define BN_EPS  1e-5f
#define LN_EPS  1e-5f
#define NPARTMAX 64
#define NBMAX 392
#define TILEB 34816          /* bytes per 128-row bf16 tile image (272B pitch) */

// ---------------- scratch (static device globals; no allocation) -------------
__device__ int   g_deg[NMAX];          // zero at entry (reset by scan_local)
__device__ int   g_offs[NMAX + 1];
__device__ int   g_cur[NMAX];
__device__ int   g_srcs[EMAX];
__device__ int   g_partoffs[NPARTMAX];
__device__ int   g_done1;              // reset by K1 last block
__device__ float g_h1[(size_t)NMAX * D2];
__device__ float g_bnpart[(size_t)NBMAX * 512];
__device__ float g_bnscale[D2];
__device__ float g_bnshift[D2];
__device__ __align__(16) unsigned char g_h0img_hi[(size_t)NBMAX * TILEB];
__device__ __align__(16) unsigned char g_h0img_lo[(size_t)NBMAX * TILEB];
__device__ __align__(16) unsigned char g_W1img_hi[69632];
__device__ __align__(16) unsigned char g_W1img_lo[69632];
__device__ __align__(16) unsigned char g_W2img_hi[69632];
__device__ __align__(16) unsigned char g_W2img_lo[69632];

// ---------------- helpers ----------------------------------------------------
__device__ __forceinline__ uint32_t smem_u32(const void* p) {
    uint32_t a;
    asm("{ .reg .u64 t; cvta.to.shared.u64 t, %1; cvt.u32.u64 %0, t; }" : "=r"(a) : "l"(p));
    return a;
}
__device__ __forceinline__ void ldsm_x4(uint32_t* r, uint32_t addr) {
    asm volatile("ldmatrix.sync.aligned.m8n8.x4.shared.b16 {%0,%1,%2,%3}, [%4];"
        : "=r"(r[0]), "=r"(r[1]), "=r"(r[2]), "=r"(r[3]) : "r"(addr));
}
__device__ __forceinline__ void mma16816(float* d, const uint32_t* a, const uint32_t* b) {
    asm volatile(
        "mma.sync.aligned.m16n8k16.row.col.f32.bf16.bf16.f32 "
        "{%0,%1,%2,%3}, {%4,%5,%6,%7}, {%8,%9}, {%0,%1,%2,%3};"
        : "+f"(d[0]), "+f"(d[1]), "+f"(d[2]), "+f"(d[3])
        : "r"(a[0]), "r"(a[1]), "r"(a[2]), "r"(a[3]), "r"(b[0]), "r"(b[1]));
}
__device__ __forceinline__ float ex2(float x) {
    float r;
    asm("ex2.approx.f32 %0, %1;" : "=f"(r) : "f"(x));
    return r;
}
#define CP_ASYNC16(dst_u32, src_ptr) \
    asm volatile("cp.async.cg.shared.global [%0], [%1], 16;" :: "r"(dst_u32), "l"(src_ptr))
#define CP_COMMIT() asm volatile("cp.async.commit_group;")
#define CP_WAIT0()  asm volatile("cp.async.wait_group 0;")

__device__ __forceinline__ void cvt8(const float* f, uint4& hv, uint4& lv) {
    unsigned h[4], l[4];
    #pragma unroll
    for (int j = 0; j < 4; j++) {
        __nv_bfloat16 a0 = __float2bfloat16(f[2*j]);
        __nv_bfloat16 a1 = __float2bfloat16(f[2*j+1]);
        __nv_bfloat16 b0 = __float2bfloat16(f[2*j]   - __bfloat162float(a0));
        __nv_bfloat16 b1 = __float2bfloat16(f[2*j+1] - __bfloat162float(a1));
        h[j] = ((unsigned)__bfloat16_as_ushort(a1) << 16) | __bfloat16_as_ushort(a0);
        l[j] = ((unsigned)__bfloat16_as_ushort(b1) << 16) | __bfloat16_as_ushort(b0);
    }
    hv = make_uint4(h[0], h[1], h[2], h[3]);
    lv = make_uint4(l[0], l[1], l[2], l[3]);
}

// ---------------- K1: weight images + histogram + (last block) chunk scan ----
__global__ void k1_init_hist(const float* __restrict__ W1, const float* __restrict__ W2,
                             const int* __restrict__ dst, int e, int n, int npart) {
    int i = blockIdx.x * 1024 + threadIdx.x;
    if (i < 32768) {                          // W1^T: n<256, k<128
        int nn = i >> 7, k = i & 127;
        float w = W1[k * 256 + nn];
        __nv_bfloat16 hi = __float2bfloat16(w);
        __nv_bfloat16 lo = __float2bfloat16(w - __bfloat162float(hi));
        int off = nn * 272 + k * 2;
        *(unsigned short*)(g_W1img_hi + off) = __bfloat16_as_ushort(hi);
        *(unsigned short*)(g_W1img_lo + off) = __bfloat16_as_ushort(lo);
    } else if (i < 65536) {                   // W2^T: n<128, k<256
        int j = i - 32768;
        int nn = j >> 8, k = j & 255;
        float w = W2[k * 128 + nn];
        __nv_bfloat16 hi = __float2bfloat16(w);
        __nv_bfloat16 lo = __float2bfloat16(w - __bfloat162float(hi));
        int off = (k >> 7) * TILEB + nn * 272 + (k & 127) * 2;
        *(unsigned short*)(g_W2img_hi + off) = __bfloat16_as_ushort(hi);
        *(unsigned short*)(g_W2img_lo + off) = __bfloat16_as_ushort(lo);
    }
    if (i < e) atomicAdd(&g_deg[dst[i]], 1);

    __threadfence();
    __shared__ int s_last;
    if (threadIdx.x == 0) s_last = (atomicAdd(&g_done1, 1) == (int)gridDim.x - 1);
    __syncthreads();
    if (!s_last) return;
    if (threadIdx.x == 0) g_done1 = 0;

    __shared__ int csum[NPARTMAX];
    __shared__ int sh[NPARTMAX];
    int t = threadIdx.x, lane = t & 31, w = t >> 5;
    for (int c = w; c < npart; c += 32) {
        int s = 0;
        for (int k = lane; k < 1024; k += 32) {
            int idx = (c << 10) + k;
            s += (idx < n) ? g_deg[idx] : 0;
        }
        #pragma unroll
        for (int o = 16; o > 0; o >>= 1) s += __shfl_xor_sync(0xffffffffu, s, o);
        if (lane == 0) csum[c] = s;
    }
    __syncthreads();
    if (t < NPARTMAX) sh[t] = (t < npart) ? csum[t] : 0;
    __syncthreads();
    for (int o = 1; o < NPARTMAX; o <<= 1) {
        int add = (t < NPARTMAX && t >= o) ? sh[t - o] : 0;
        __syncthreads();
        if (t < NPARTMAX) sh[t] += add;
        __syncthreads();
    }
    if (t < npart) g_partoffs[t] = sh[t] - csum[t];
    if (t == npart - 1) g_offs[n] = sh[t];
}

// ---------------- local scan within each 1024-chunk (+ g_deg reset) ----------
__global__ void scan_local_kernel(int n) {
    __shared__ int warpsums[32];
    int t = threadIdx.x, lane = t & 31, w = t >> 5;
    int i = blockIdx.x * 1024 + t;
    int v = (i < n) ? g_deg[i] : 0;
    int s = v;
    #pragma unroll
    for (int o = 1; o < 32; o <<= 1) {
        int u = __shfl_up_sync(0xffffffffu, s, o);
        if (lane >= o) s += u;
    }
    if (lane == 31) warpsums[w] = s;
    __syncthreads();
    if (w == 0) {
        int ws = warpsums[lane];
        #pragma unroll
        for (int o = 1; o < 32; o <<= 1) {
            int u = __shfl_up_sync(0xffffffffu, ws, o);
            if (lane >= o) ws += u;
        }
        warpsums[lane] = ws;
    }
    __syncthreads();
    if (i < n) {
        int ex = g_partoffs[blockIdx.x] + s - v + (w > 0 ? warpsums[w - 1] : 0);
        g_offs[i] = ex;
        g_cur[i] = ex;
        g_deg[i] = 0;
    }
}

__global__ void scatter_kernel(const int* __restrict__ src, const int* __restrict__ dst, int e) {
    int i = blockIdx.x * blockDim.x + threadIdx.x;
    if (i < e) {
        int pos = atomicAdd(&g_cur[dst[i]], 1);
        g_srcs[pos] = src[i];
    }
}

// ---------------- one-pass softmax aggregation (warp per node) ---------------
// exp(t*(relu+eps)) = exp(t*eps)*exp(t*relu): constant factor cancels in the
// n/d ratio, so exponent uses relu only; the eps term in the numerator is
// folded back once per node: n = n' + eps*d. ex2.approx with prefolded log2e.
__global__ void agg_kernel(const float* __restrict__ x, const float* __restrict__ t_ptr, int n) {
    int gw   = (blockIdx.x * blockDim.x + threadIdx.x) >> 5;
    int lane = threadIdx.x & 31;
    if (gw >= n) return;
    float c = (*t_ptr) * 1.4426950408889634f;   // t * log2(e)
    int beg = g_offs[gw], end = g_offs[gw + 1];

    float n0 = 0.f, n1 = 0.f, n2 = 0.f, n3 = 0.f;
    float d0 = 0.f, d1 = 0.f, d2 = 0.f, d3 = 0.f;
    int e = beg;
    int e4 = beg + ((end - beg) & ~3);
    for (; e < e4; e += 4) {
        float4 qa0 = __ldg((const float4*)(x + (size_t)__ldg(&g_srcs[e    ]) * D) + lane);
        float4 qa1 = __ldg((const float4*)(x + (size_t)__ldg(&g_srcs[e + 1]) * D) + lane);
        float4 qa2 = __ldg((const float4*)(x + (size_t)__ldg(&g_srcs[e + 2]) * D) + lane);
        float4 qa3 = __ldg((const float4*)(x + (size_t)__ldg(&g_srcs[e + 3]) * D) + lane);
        #pragma unroll
        for (int j = 0; j < 4; j++) {
            float4 q = (j == 0) ? qa0 : (j == 1) ? qa1 : (j == 2) ? qa2 : qa3;
            float v0 = fmaxf(q.x, 0.f), v1 = fmaxf(q.y, 0.f);
            float v2 = fmaxf(q.z, 0.f), v3 = fmaxf(q.w, 0.f);
            float e0 = ex2(v0 * c), e1 = ex2(v1 * c);
            float e2 = ex2(v2 * c), e3 = ex2(v3 * c);
            d0 += e0; d1 += e1; d2 += e2; d3 += e3;
            n0 = fmaf(e0, v0, n0); n1 = fmaf(e1, v1, n1);
            n2 = fmaf(e2, v2, n2); n3 = fmaf(e3, v3, n3);
        }
    }
    for (; e < end; e++) {
        float4 q = __ldg((const float4*)(x + (size_t)__ldg(&g_srcs[e]) * D) + lane);
        float v0 = fmaxf(q.x, 0.f), v1 = fmaxf(q.y, 0.f);
        float v2 = fmaxf(q.z, 0.f), v3 = fmaxf(q.w, 0.f);
        float e0 = ex2(v0 * c), e1 = ex2(v1 * c);
        float e2 = ex2(v2 * c), e3 = ex2(v3 * c);
        d0 += e0; d1 += e1; d2 += e2; d3 += e3;
        n0 = fmaf(e0, v0, n0); n1 = fmaf(e1, v1, n1);
        n2 = fmaf(e2, v2, n2); n3 = fmaf(e3, v3, n3);
    }
    float4 xq = __ldg((const float4*)(x + (size_t)gw * D) + lane);
    float hx = (n0 + MSG_EPS * d0) / (d0 + SM_EPS) + xq.x;
    float hy = (n1 + MSG_EPS * d1) / (d1 + SM_EPS) + xq.y;
    float hz = (n2 + MSG_EPS * d2) / (d2 + SM_EPS) + xq.z;
    float hw = (n3 + MSG_EPS * d3) / (d3 + SM_EPS) + xq.w;

    // write bf16 hi/lo tile images in gemm1's smem layout (272B pitch)
    __nv_bfloat16 bx = __float2bfloat16(hx), by = __float2bfloat16(hy);
    __nv_bfloat16 bz = __float2bfloat16(hz), bw = __float2bfloat16(hw);
    uint32_t hi0 = ((uint32_t)__bfloat16_as_ushort(by) << 16) | __bfloat16_as_ushort(bx);
    uint32_t hi1 = ((uint32_t)__bfloat16_as_ushort(bw) << 16) | __bfloat16_as_ushort(bz);
    __nv_bfloat16 rx = __float2bfloat16(hx - __bfloat162float(bx));
    __nv_bfloat16 ry = __float2bfloat16(hy - __bfloat162float(by));
    __nv_bfloat16 rz = __float2bfloat16(hz - __bfloat162float(bz));
    __nv_bfloat16 rw = __float2bfloat16(hw - __bfloat162float(bw));
    uint32_t lo0 = ((uint32_t)__bfloat16_as_ushort(ry) << 16) | __bfloat16_as_ushort(rx);
    uint32_t lo1 = ((uint32_t)__bfloat16_as_ushort(rw) << 16) | __bfloat16_as_ushort(rz);
    size_t off = (size_t)(gw >> 7) * TILEB + (gw & 127) * 272 + lane * 8;
    *(uint2*)(g_h0img_hi + off) = make_uint2(hi0, hi1);
    *(uint2*)(g_h0img_lo + off) = make_uint2(lo0, lo1);
}

// ---------------- GEMM1 (persistent, cp.async A images): h1 = h0 @ W1 + b1 ---
#define G1_AHI  0
#define G1_ALO  34816
#define G1_BHI  69632
#define G1_BLO  139264
#define G1_BIAS 208896
#define G1_STAT 209920
#define G1_SMEM 214016

__global__ __launch_bounds__(256) void gemm1_mma(const float* __restrict__ b1, int M, int nb) {
    extern __shared__ char smem[];
    uint32_t sb = smem_u32(smem);
    int tid = threadIdx.x, w = tid >> 5, lane = tid & 31;
    float* b1s = (float*)(smem + G1_BIAS);
    b1s[tid] = __ldg(&b1[tid]);

    // B tiles + first A tile via cp.async
    for (int u = tid; u < 4352; u += 256) {
        CP_ASYNC16(sb + G1_BHI + u * 16, (const char*)g_W1img_hi + u * 16);
        CP_ASYNC16(sb + G1_BLO + u * 16, (const char*)g_W1img_lo + u * 16);
    }
    {
        size_t abase = (size_t)blockIdx.x * TILEB;
        for (int u = tid; u < 2176; u += 256) {
            CP_ASYNC16(sb + G1_AHI + u * 16, (const char*)g_h0img_hi + abase + u * 16);
            CP_ASYNC16(sb + G1_ALO + u * 16, (const char*)g_h0img_lo + abase + u * 16);
        }
    }
    CP_COMMIT();

    int m0 = (w & 1) * 64, n0 = (w >> 1) * 64;
    int lr = lane & 7, mid = lane >> 3;
    uint32_t aoff = (uint32_t)((m0 + lr + ((mid & 1) << 3)) * 272 + ((mid >> 1) << 4));
    uint32_t boff = (uint32_t)((n0 + lr + ((mid >> 1) << 3)) * 272 + ((mid & 1) << 4));
    uint32_t aHb = sb + G1_AHI + aoff, aLb = sb + G1_ALO + aoff;
    uint32_t bHb = sb + G1_BHI + boff, bLb = sb + G1_BLO + boff;
    float* s_sum = (float*)(smem + G1_STAT);
    float* s_sq  = s_sum + 512;

    for (int rb = blockIdx.x; rb < nb; rb += gridDim.x) {
        int row0 = rb * 128;
        CP_WAIT0();
        __syncthreads();

        float acc[4][8][4];
        #pragma unroll
        for (int i = 0; i < 4; i++)
            #pragma unroll
            for (int j = 0; j < 8; j++)
                #pragma unroll
                for (int q = 0; q < 4; q++) acc[i][j][q] = 0.f;

        #pragma unroll
        for (int ks = 0; ks < 8; ks++) {
            uint32_t kb = ks << 5;
            uint32_t aH[4][4], aL[4][4];
            #pragma unroll
            for (int mb = 0; mb < 4; mb++) {
                ldsm_x4(aH[mb], aHb + mb * 4352 + kb);
                ldsm_x4(aL[mb], aLb + mb * 4352 + kb);
            }
            #pragma unroll
            for (int nbp = 0; nbp < 4; nbp++) {
                uint32_t bh[4], bl[4];
                ldsm_x4(bh, bHb + nbp * 4352 + kb);
                ldsm_x4(bl, bLb + nbp * 4352 + kb);
                #pragma unroll
                for (int mb = 0; mb < 4; mb++) {
                    mma16816(acc[mb][2*nbp],     aH[mb], bh);
                    mma16816(acc[mb][2*nbp],     aH[mb], bl);
                    mma16816(acc[mb][2*nbp],     aL[mb], bh);
                    mma16816(acc[mb][2*nbp + 1], aH[mb], bh + 2);
                    mma16816(acc[mb][2*nbp + 1], aH[mb], bl + 2);
                    mma16816(acc[mb][2*nbp + 1], aL[mb], bh + 2);
                }
            }
        }
        __syncthreads();   // all warps done reading A

        // prefetch next row-block's A while we run the epilogue
        int rbn = rb + gridDim.x;
        if (rbn < nb) {
            size_t abase = (size_t)rbn * TILEB;
            for (int u = tid; u < 2176; u += 256) {
                CP_ASYNC16(sb + G1_AHI + u * 16, (const char*)g_h0img_hi + abase + u * 16);
                CP_ASYNC16(sb + G1_ALO + u * 16, (const char*)g_h0img_lo + abase + u * 16);
            }
        }
        CP_COMMIT();

        // epilogue: + bias, store h1, column partials (atomic-free)
        int mtop = row0 + m0 + (lane >> 2);
        int nc = n0 + 2 * (lane & 3);
        float cs[8][2], cq[8][2];
        #pragma unroll
        for (int j = 0; j < 8; j++) { cs[j][0] = cs[j][1] = cq[j][0] = cq[j][1] = 0.f; }
        #pragma unroll
        for (int mb = 0; mb < 4; mb++) {
            int r0 = mtop + mb * 16;
            bool gd0 = r0 < M, gd1 = (r0 + 8) < M;
            #pragma unroll
            for (int nbq = 0; nbq < 8; nbq++) {
                int n = nc + nbq * 8;
                float bv0 = b1s[n], bv1 = b1s[n + 1];
                float o0 = acc[mb][nbq][0] + bv0, o1 = acc[mb][nbq][1] + bv1;
                float o2 = acc[mb][nbq][2] + bv0, o3 = acc[mb][nbq][3] + bv1;
                size_t r1 = (size_t)r0 * 256 + n;
                *(float2*)(g_h1 + r1)           = make_float2(o0, o1);
                *(float2*)(g_h1 + r1 + 8 * 256) = make_float2(o2, o3);
                cs[nbq][0] += (gd0 ? o0 : 0.f) + (gd1 ? o2 : 0.f);
                cs[nbq][1] += (gd0 ? o1 : 0.f) + (gd1 ? o3 : 0.f);
                cq[nbq][0] += (gd0 ? o0 * o0 : 0.f) + (gd1 ? o2 * o2 : 0.f);
                cq[nbq][1] += (gd0 ? o1 * o1 : 0.f) + (gd1 ? o3 * o3 : 0.f);
            }
        }
        #pragma unroll
        for (int nbq = 0; nbq < 8; nbq++) {
            #pragma unroll
            for (int o = 16; o >= 4; o >>= 1) {
                cs[nbq][0] += __shfl_down_sync(0xffffffffu, cs[nbq][0], o);
                cs[nbq][1] += __shfl_down_sync(0xffffffffu, cs[nbq][1], o);
                cq[nbq][0] += __shfl_down_sync(0xffffffffu, cq[nbq][0], o);
                cq[nbq][1] += __shfl_down_sync(0xffffffffu, cq[nbq][1], o);
            }
        }
        if (lane < 4) {
            #pragma unroll
            for (int nbq = 0; nbq < 8; nbq++) {
                int cl = nbq * 8 + lane * 2;
                s_sum[w * 64 + cl]     = cs[nbq][0];
                s_sum[w * 64 + cl + 1] = cs[nbq][1];
                s_sq [w * 64 + cl]     = cq[nbq][0];
                s_sq [w * 64 + cl + 1] = cq[nbq][1];
            }
        }
        __syncthreads();
        {
            int col = tid;
            int g = col >> 6, cl = col & 63;
            float ssum = s_sum[(2 * g) * 64 + cl] + s_sum[(2 * g + 1) * 64 + cl];
            float ssq  = s_sq [(2 * g) * 64 + cl] + s_sq [(2 * g + 1) * 64 + cl];
            g_bnpart[(size_t)rb * 512 + col]       = ssum;
            g_bnpart[(size_t)rb * 512 + 256 + col] = ssq;
        }
    }
}

// ---------------- BN finalize ------------------------------------------------
__global__ void bnfinal_kernel(const float* __restrict__ gamma,
                               const float* __restrict__ beta, int n, int nblk) {
    __shared__ float sh[512];
    int t = threadIdx.x;      // 512
    float s = 0.f;
    for (int b = 0; b < nblk; b++) s += g_bnpart[(size_t)b * 512 + t];
    sh[t] = s;
    __syncthreads();
    if (t < D2) {
        float inv_n = 1.f / (float)n;
        float mu  = sh[t] * inv_n;
        float var = sh[t + 256] * inv_n - mu * mu;
        float sc  = gamma[t] * rsqrtf(var + BN_EPS);
        g_bnscale[t] = sc;
        g_bnshift[t] = beta[t] - mu * sc;
    }
}

// ---------------- GEMM2 (persistent): out = x + relu(LN(relu(BN(h1))@W2+b2)) -
#define G2_AHI   0
#define G2_ALO   34816
#define G2_B     69632
#define G2_CST   0
#define G2_CONST 208896
#define G2_SMEM  212480

__global__ __launch_bounds__(256) void gemm2_mma(const float* __restrict__ b2,
                                                 const float* __restrict__ ln_gamma,
                                                 const float* __restrict__ ln_beta,
                                                 const float* __restrict__ x,
                                                 float* __restrict__ out, int M, int nb) {
    extern __shared__ char smem[];
    uint32_t sb = smem_u32(smem);
    int tid = threadIdx.x, w = tid >> 5, lane = tid & 31;

    float* s_sc = (float*)(smem + G2_CONST);
    float* s_sh = s_sc + 256;
    float* s_b2 = s_sh + 256;
    float* s_lg = s_b2 + 128;
    float* s_lb = s_lg + 128;
    s_sc[tid] = g_bnscale[tid];
    s_sh[tid] = g_bnshift[tid];
    if (tid < 128) {
        s_b2[tid] = __ldg(&b2[tid]);
        s_lg[tid] = __ldg(&ln_gamma[tid]);
        s_lb[tid] = __ldg(&ln_beta[tid]);
    }
    for (int u = tid; u < 2176; u += 256) {
        #pragma unroll
        for (int p = 0; p < 2; p++) {
            CP_ASYNC16(sb + G2_B + p * 69632 + u * 16,         (const char*)g_W2img_hi + p * TILEB + u * 16);
            CP_ASYNC16(sb + G2_B + p * 69632 + 34816 + u * 16, (const char*)g_W2img_lo + p * TILEB + u * 16);
        }
    }
    CP_COMMIT();

    int m0 = (w & 1) * 64, n0 = (w >> 1) * 32;
    int lr = lane & 7, mid = lane >> 3;
    uint32_t aoff = (uint32_t)((m0 + lr + ((mid & 1) << 3)) * 272 + ((mid >> 1) << 4));
    uint32_t boff = (uint32_t)((n0 + lr + ((mid >> 1) << 3)) * 272 + ((mid & 1) << 4));
    uint32_t aHb = sb + G2_AHI + aoff, aLb = sb + G2_ALO + aoff;

    for (int rb = blockIdx.x; rb < nb; rb += gridDim.x) {
        int row0 = rb * 128;
        float acc[4][4][4];
        #pragma unroll
        for (int i = 0; i < 4; i++)
            #pragma unroll
            for (int j = 0; j < 4; j++)
                #pragma unroll
                for (int q = 0; q < 4; q++) acc[i][j][q] = 0.f;

        for (int p = 0; p < 2; p++) {
            __syncthreads();
            for (int u = tid; u < 2048; u += 256) {
                int m = u >> 4, g = u & 15;
                int kc = (p << 7) + (g << 3);
                const float4* hr = (const float4*)(g_h1 + (size_t)(row0 + m) * 256 + kc);
                float4 q0 = hr[0], q1 = hr[1];
                float f[8] = {q0.x, q0.y, q0.z, q0.w, q1.x, q1.y, q1.z, q1.w};
                #pragma unroll
                for (int j = 0; j < 8; j++)
                    f[j] = fmaxf(fmaf(f[j], s_sc[kc + j], s_sh[kc + j]), 0.f);
                uint4 hv, lv; cvt8(f, hv, lv);
                int off = m * 272 + g * 16;
                *(uint4*)(smem + G2_AHI + off) = hv;
                *(uint4*)(smem + G2_ALO + off) = lv;
            }
            CP_WAIT0();
            __syncthreads();

            uint32_t bHb = sb + G2_B + p * 69632 + boff;
            uint32_t bLb = bHb + 34816;
            #pragma unroll
            for (int ks = 0; ks < 8; ks++) {
                uint32_t kb = ks << 5;
                uint32_t aH[4][4], aL[4][4];
                #pragma unroll
                for (int mb = 0; mb < 4; mb++) {
                    ldsm_x4(aH[mb], aHb + mb * 4352 + kb);
                    ldsm_x4(aL[mb], aLb + mb * 4352 + kb);
                }
                #pragma unroll
                for (int nbp = 0; nbp < 2; nbp++) {
                    uint32_t bh[4], bl[4];
                    ldsm_x4(bh, bHb + nbp * 4352 + kb);
                    ldsm_x4(bl, bLb + nbp * 4352 + kb);
                    #pragma unroll
                    for (int mb = 0; mb < 4; mb++) {
                        mma16816(acc[mb][2*nbp],     aH[mb], bh);
                        mma16816(acc[mb][2*nbp],     aH[mb], bl);
                        mma16816(acc[mb][2*nbp],     aL[mb], bh);
                        mma16816(acc[mb][2*nbp + 1], aH[mb], bh + 2);
                        mma16816(acc[mb][2*nbp + 1], aH[mb], bl + 2);
                        mma16816(acc[mb][2*nbp + 1], aL[mb], bh + 2);
                    }
                }
            }
        }
        __syncthreads();

        float* Cs = (float*)(smem + G2_CST);
        {
            int mtop = m0 + (lane >> 2), nc = n0 + 2 * (lane & 3);
            #pragma unroll
            for (int mb = 0; mb < 4; mb++) {
                #pragma unroll
                for (int nbq = 0; nbq < 4; nbq++) {
                    int n = nc + nbq * 8;
                    int rr = mtop + mb * 16;
                    *(float2*)(Cs + rr * 132 + n)       = make_float2(acc[mb][nbq][0], acc[mb][nbq][1]);
                    *(float2*)(Cs + (rr + 8) * 132 + n) = make_float2(acc[mb][nbq][2], acc[mb][nbq][3]);
                }
            }
        }
        __syncthreads();

        if (tid < 128) {
            int grow = row0 + tid;
            const float* cr = Cs + tid * 132;
            float sum = 0.f, sq = 0.f;
            #pragma unroll
            for (int c = 0; c < 128; c += 4) {
                float4 q = *(const float4*)(cr + c);
                float v0 = q.x + s_b2[c], v1 = q.y + s_b2[c+1];
                float v2 = q.z + s_b2[c+2], v3 = q.w + s_b2[c+3];
                sum += v0 + v1 + v2 + v3;
                sq  += v0*v0 + v1*v1 + v2*v2 + v3*v3;
            }
            float mu = sum * (1.f / D);
            float var = sq * (1.f / D) - mu * mu;
            float rr = rsqrtf(var + LN_EPS);
            if (grow < M) {
                const float4* xr = (const float4*)(x + (size_t)grow * D);
                float4* po = (float4*)(out + (size_t)grow * D);
                #pragma unroll
                for (int c = 0; c < 128; c += 4) {
                    float4 q = *(const float4*)(cr + c);
                    float4 xv = __ldg(xr + (c >> 2));
                    float4 o;
                    o.x = xv.x + fmaxf((q.x + s_b2[c]   - mu) * rr * s_lg[c]   + s_lb[c],   0.f);
                    o.y = xv.y + fmaxf((q.y + s_b2[c+1] - mu) * rr * s_lg[c+1] + s_lb[c+1], 0.f);
                    o.z = xv.z + fmaxf((q.z + s_b2[c+2] - mu) * rr * s_lg[c+2] + s_lb[c+2], 0.f);
                    o.w = xv.w + fmaxf((q.w + s_b2[c+3] - mu) * rr * s_lg[c+3] + s_lb[c+3], 0.f);
                    po[c >> 2] = o;
                }
            }
        }
    }
}

// ---------------- launcher ---------------------------------------------------
extern "C" void kernel_launch(void* const* d_in, const int* in_sizes, int n_in,
                              void* d_out, int out_size) {
    const float* x        = (const float*)d_in[0];
    const int*   ei       = (const int*)  d_in[1];
    const float* t_ptr    = (const float*)d_in[2];
    const float* W1       = (const float*)d_in[3];
    const float* b1       = (const float*)d_in[4];
    const float* bn_gamma = (const float*)d_in[5];
    const float* bn_beta  = (const float*)d_in[6];
    const float* W2       = (const float*)d_in[7];
    const float* b2       = (const float*)d_in[8];
    const float* ln_gamma = (const float*)d_in[9];
    const float* ln_beta  = (const float*)d_in[10];
    float* out = (float*)d_out;

    int n = in_sizes[0] / D;
    int e = in_sizes[1] / 2;
    const int* src = ei;
    const int* dst = ei + e;
    int nb = (n + 127) / 128;
    int npart = (n + 1023) / 1024;
    int gpers = nb < 152 ? nb : 152;
    int hb = ((e > 65536 ? e : 65536) + 1023) / 1024;

    cudaFuncSetAttribute(gemm1_mma, cudaFuncAttributeMaxDynamicSharedMemorySize, G1_SMEM);
    cudaFuncSetAttribute(gemm2_mma, cudaFuncAttributeMaxDynamicSharedMemorySize, G2_SMEM);

    k1_init_hist<<<hb, 1024>>>(W1, W2, dst, e, n, npart);
    scan_local_kernel<<<npart, 1024>>>(n);
    scatter_kernel<<<(e + 255) / 256, 256>>>(src, dst, e);
    agg_kernel<<<(n * 32 + 255) / 256, 256>>>(x, t_ptr, n);
    gemm1_mma<<<gpers, 256, G1_SMEM>>>(b1, n, nb);
    bnfinal_kernel<<<1, 512>>>(bn_gamma, bn_beta, n, nb);
    gemm2_mma<<<gpers, 256, G2_SMEM>>>(b2, ln_gamma, ln_beta, x, out, n, nb);
}

// round 13
// speedup vs baseline: 1.6221x; 1.0112x over previous
#include <cuda_runtime.h>
#include <cuda_bf16.h>
#include <cuda_fp16.h>
#include <math_constants.h>
#include <cstdint>

#define NMAX 50176
#define EMAX 800000
#define D    128
#define D2   256
#define MSG_EPS 1e-7f
#define SM_EPS  1e-16f
#define BN_EPS  1e-5f
#define LN_EPS  1e-5f
#define NPARTMAX 64
#define NBMAX 392
#define TILEB 34816          /* bytes per 128-row bf16 tile image (272B pitch) */

// ---------------- scratch (static device globals; no allocation) -------------
__device__ int   g_deg[NMAX];          // zero at entry (reset by scan_local)
__device__ int   g_offs[NMAX + 1];
__device__ int   g_cur[NMAX];
__device__ int   g_srcs[EMAX];
__device__ int   g_partoffs[NPARTMAX];
__device__ int   g_done1;              // reset by K1 last block
__device__ float g_h1[(size_t)NMAX * D2];
__device__ float g_bnpart[(size_t)NBMAX * 512];
__device__ float g_bnscale[D2];
__device__ float g_bnshift[D2];
__device__ __align__(16) uint32_t g_ew[(size_t)NMAX * D];   // half2(E, W) per feature
__device__ __align__(16) unsigned char g_h0img_hi[(size_t)NBMAX * TILEB];
__device__ __align__(16) unsigned char g_h0img_lo[(size_t)NBMAX * TILEB];
__device__ __align__(16) unsigned char g_W1img_hi[69632];
__device__ __align__(16) unsigned char g_W1img_lo[69632];
__device__ __align__(16) unsigned char g_W2img_hi[69632];
__device__ __align__(16) unsigned char g_W2img_lo[69632];

// ---------------- helpers ----------------------------------------------------
__device__ __forceinline__ uint32_t smem_u32(const void* p) {
    uint32_t a;
    asm("{ .reg .u64 t; cvta.to.shared.u64 t, %1; cvt.u32.u64 %0, t; }" : "=r"(a) : "l"(p));
    return a;
}
__device__ __forceinline__ void ldsm_x4(uint32_t* r, uint32_t addr) {
    asm volatile("ldmatrix.sync.aligned.m8n8.x4.shared.b16 {%0,%1,%2,%3}, [%4];"
        : "=r"(r[0]), "=r"(r[1]), "=r"(r[2]), "=r"(r[3]) : "r"(addr));
}
__device__ __forceinline__ void mma16816(float* d, const uint32_t* a, const uint32_t* b) {
    asm volatile(
        "mma.sync.aligned.m16n8k16.row.col.f32.bf16.bf16.f32 "
        "{%0,%1,%2,%3}, {%4,%5,%6,%7}, {%8,%9}, {%0,%1,%2,%3};"
        : "+f"(d[0]), "+f"(d[1]), "+f"(d[2]), "+f"(d[3])
        : "r"(a[0]), "r"(a[1]), "r"(a[2]), "r"(a[3]), "r"(b[0]), "r"(b[1]));
}
__device__ __forceinline__ float ex2(float x) {
    float r;
    asm("ex2.approx.f32 %0, %1;" : "=f"(r) : "f"(x));
    return r;
}
#define CP_ASYNC16(dst_u32, src_ptr) \
    asm volatile("cp.async.cg.shared.global [%0], [%1], 16;" :: "r"(dst_u32), "l"(src_ptr))
#define CP_COMMIT() asm volatile("cp.async.commit_group;")
#define CP_WAIT0()  asm volatile("cp.async.wait_group 0;")

__device__ __forceinline__ void cvt8(const float* f, uint4& hv, uint4& lv) {
    unsigned h[4], l[4];
    #pragma unroll
    for (int j = 0; j < 4; j++) {
        __nv_bfloat16 a0 = __float2bfloat16(f[2*j]);
        __nv_bfloat16 a1 = __float2bfloat16(f[2*j+1]);
        __nv_bfloat16 b0 = __float2bfloat16(f[2*j]   - __bfloat162float(a0));
        __nv_bfloat16 b1 = __float2bfloat16(f[2*j+1] - __bfloat162float(a1));
        h[j] = ((unsigned)__bfloat16_as_ushort(a1) << 16) | __bfloat16_as_ushort(a0);
        l[j] = ((unsigned)__bfloat16_as_ushort(b1) << 16) | __bfloat16_as_ushort(b0);
    }
    hv = make_uint4(h[0], h[1], h[2], h[3]);
    lv = make_uint4(l[0], l[1], l[2], l[3]);
}
__device__ __forceinline__ uint32_t packEW(float xv, float c) {
    float v = fmaxf(xv, 0.f);
    float e = ex2(v * c);
    __half2 h = __floats2half2_rn(e, e * v);
    return *(uint32_t*)&h;
}

// ---------------- K1: weight images + EW table + histogram + chunk scan ------
__global__ void k1_init_hist(const float* __restrict__ W1, const float* __restrict__ W2,
                             const float* __restrict__ x, const float* __restrict__ t_ptr,
                             const int* __restrict__ dst, int e, int n, int npart) {
    int i = blockIdx.x * 1024 + threadIdx.x;
    if (i < 32768) {                          // W1^T: n<256, k<128
        int nn = i >> 7, k = i & 127;
        float w = W1[k * 256 + nn];
        __nv_bfloat16 hi = __float2bfloat16(w);
        __nv_bfloat16 lo = __float2bfloat16(w - __bfloat162float(hi));
        int off = nn * 272 + k * 2;
        *(unsigned short*)(g_W1img_hi + off) = __bfloat16_as_ushort(hi);
        *(unsigned short*)(g_W1img_lo + off) = __bfloat16_as_ushort(lo);
    } else if (i < 65536) {                   // W2^T: n<128, k<256
        int j = i - 32768;
        int nn = j >> 8, k = j & 255;
        float w = W2[k * 128 + nn];
        __nv_bfloat16 hi = __float2bfloat16(w);
        __nv_bfloat16 lo = __float2bfloat16(w - __bfloat162float(hi));
        int off = (k >> 7) * TILEB + nn * 272 + (k & 127) * 2;
        *(unsigned short*)(g_W2img_hi + off) = __bfloat16_as_ushort(hi);
        *(unsigned short*)(g_W2img_lo + off) = __bfloat16_as_ushort(lo);
    }
    // EW table: thread i handles 4 features (one float4) of node i>>5
    if (i < n * 32) {
        float c = __ldg(t_ptr) * 1.4426950408889634f;
        int node = i >> 5, l = i & 31;
        float4 q = __ldg((const float4*)(x + (size_t)node * D) + l);
        uint4 u;
        u.x = packEW(q.x, c);
        u.y = packEW(q.y, c);
        u.z = packEW(q.z, c);
        u.w = packEW(q.w, c);
        *(uint4*)(g_ew + (size_t)node * D + l * 4) = u;
    }
    if (i < e) atomicAdd(&g_deg[dst[i]], 1);

    __threadfence();
    __shared__ int s_last;
    if (threadIdx.x == 0) s_last = (atomicAdd(&g_done1, 1) == (int)gridDim.x - 1);
    __syncthreads();
    if (!s_last) return;
    if (threadIdx.x == 0) g_done1 = 0;

    __shared__ int csum[NPARTMAX];
    __shared__ int sh[NPARTMAX];
    int t = threadIdx.x, lane = t & 31, w = t >> 5;
    for (int c2 = w; c2 < npart; c2 += 32) {
        int s = 0;
        for (int k = lane; k < 1024; k += 32) {
            int idx = (c2 << 10) + k;
            s += (idx < n) ? g_deg[idx] : 0;
        }
        #pragma unroll
        for (int o = 16; o > 0; o >>= 1) s += __shfl_xor_sync(0xffffffffu, s, o);
        if (lane == 0) csum[c2] = s;
    }
    __syncthreads();
    if (t < NPARTMAX) sh[t] = (t < npart) ? csum[t] : 0;
    __syncthreads();
    for (int o = 1; o < NPARTMAX; o <<= 1) {
        int add = (t < NPARTMAX && t >= o) ? sh[t - o] : 0;
        __syncthreads();
        if (t < NPARTMAX) sh[t] += add;
        __syncthreads();
    }
    if (t < npart) g_partoffs[t] = sh[t] - csum[t];
    if (t == npart - 1) g_offs[n] = sh[t];
}

// ---------------- local scan within each 1024-chunk (+ g_deg reset) ----------
__global__ void scan_local_kernel(int n) {
    __shared__ int warpsums[32];
    int t = threadIdx.x, lane = t & 31, w = t >> 5;
    int i = blockIdx.x * 1024 + t;
    int v = (i < n) ? g_deg[i] : 0;
    int s = v;
    #pragma unroll
    for (int o = 1; o < 32; o <<= 1) {
        int u = __shfl_up_sync(0xffffffffu, s, o);
        if (lane >= o) s += u;
    }
    if (lane == 31) warpsums[w] = s;
    __syncthreads();
    if (w == 0) {
        int ws = warpsums[lane];
        #pragma unroll
        for (int o = 1; o < 32; o <<= 1) {
            int u = __shfl_up_sync(0xffffffffu, ws, o);
            if (lane >= o) ws += u;
        }
        warpsums[lane] = ws;
    }
    __syncthreads();
    if (i < n) {
        int ex = g_partoffs[blockIdx.x] + s - v + (w > 0 ? warpsums[w - 1] : 0);
        g_offs[i] = ex;
        g_cur[i] = ex;
        g_deg[i] = 0;
    }
}

__global__ void scatter_kernel(const int* __restrict__ src, const int* __restrict__ dst, int e) {
    int i = blockIdx.x * blockDim.x + threadIdx.x;
    if (i < e) {
        int pos = atomicAdd(&g_cur[dst[i]], 1);
        g_srcs[pos] = src[i];
    }
}

// ---------------- one-pass softmax aggregation via EW table ------------------
// n/d with e-factors precomputed per source node (fp16): d = sum E, n = sum W.
__device__ __forceinline__ void accEW(uint4 u, float& d0, float& n0, float& d1, float& n1,
                                      float& d2, float& n2, float& d3, float& n3) {
    float2 f;
    f = __half22float2(*(__half2*)&u.x); d0 += f.x; n0 += f.y;
    f = __half22float2(*(__half2*)&u.y); d1 += f.x; n1 += f.y;
    f = __half22float2(*(__half2*)&u.z); d2 += f.x; n2 += f.y;
    f = __half22float2(*(__half2*)&u.w); d3 += f.x; n3 += f.y;
}

__global__ void agg_kernel(const float* __restrict__ x, int n) {
    int gw   = (blockIdx.x * blockDim.x + threadIdx.x) >> 5;
    int lane = threadIdx.x & 31;
    if (gw >= n) return;
    int beg = g_offs[gw], end = g_offs[gw + 1];

    float n0 = 0.f, n1 = 0.f, n2 = 0.f, n3 = 0.f;
    float d0 = 0.f, d1 = 0.f, d2 = 0.f, d3 = 0.f;
    int e = beg;
    int e4 = beg + ((end - beg) & ~3);
    for (; e < e4; e += 4) {
        uint4 u0 = __ldg((const uint4*)(g_ew + (size_t)__ldg(&g_srcs[e    ]) * D) + lane);
        uint4 u1 = __ldg((const uint4*)(g_ew + (size_t)__ldg(&g_srcs[e + 1]) * D) + lane);
        uint4 u2 = __ldg((const uint4*)(g_ew + (size_t)__ldg(&g_srcs[e + 2]) * D) + lane);
        uint4 u3 = __ldg((const uint4*)(g_ew + (size_t)__ldg(&g_srcs[e + 3]) * D) + lane);
        accEW(u0, d0, n0, d1, n1, d2, n2, d3, n3);
        accEW(u1, d0, n0, d1, n1, d2, n2, d3, n3);
        accEW(u2, d0, n0, d1, n1, d2, n2, d3, n3);
        accEW(u3, d0, n0, d1, n1, d2, n2, d3, n3);
    }
    for (; e < end; e++) {
        uint4 u = __ldg((const uint4*)(g_ew + (size_t)__ldg(&g_srcs[e]) * D) + lane);
        accEW(u, d0, n0, d1, n1, d2, n2, d3, n3);
    }
    float4 xq = __ldg((const float4*)(x + (size_t)gw * D) + lane);
    float hx = (n0 + MSG_EPS * d0) / (d0 + SM_EPS) + xq.x;
    float hy = (n1 + MSG_EPS * d1) / (d1 + SM_EPS) + xq.y;
    float hz = (n2 + MSG_EPS * d2) / (d2 + SM_EPS) + xq.z;
    float hw = (n3 + MSG_EPS * d3) / (d3 + SM_EPS) + xq.w;

    // write bf16 hi/lo tile images in gemm1's smem layout (272B pitch)
    __nv_bfloat16 bx = __float2bfloat16(hx), by = __float2bfloat16(hy);
    __nv_bfloat16 bz = __float2bfloat16(hz), bw = __float2bfloat16(hw);
    uint32_t hi0 = ((uint32_t)__bfloat16_as_ushort(by) << 16) | __bfloat16_as_ushort(bx);
    uint32_t hi1 = ((uint32_t)__bfloat16_as_ushort(bw) << 16) | __bfloat16_as_ushort(bz);
    __nv_bfloat16 rx = __float2bfloat16(hx - __bfloat162float(bx));
    __nv_bfloat16 ry = __float2bfloat16(hy - __bfloat162float(by));
    __nv_bfloat16 rz = __float2bfloat16(hz - __bfloat162float(bz));
    __nv_bfloat16 rw = __float2bfloat16(hw - __bfloat162float(bw));
    uint32_t lo0 = ((uint32_t)__bfloat16_as_ushort(ry) << 16) | __bfloat16_as_ushort(rx);
    uint32_t lo1 = ((uint32_t)__bfloat16_as_ushort(rw) << 16) | __bfloat16_as_ushort(rz);
    size_t off = (size_t)(gw >> 7) * TILEB + (gw & 127) * 272 + lane * 8;
    *(uint2*)(g_h0img_hi + off) = make_uint2(hi0, hi1);
    *(uint2*)(g_h0img_lo + off) = make_uint2(lo0, lo1);
}

// ---------------- GEMM1 (persistent, cp.async A images): h1 = h0 @ W1 + b1 ---
#define G1_AHI  0
#define G1_ALO  34816
#define G1_BHI  69632
#define G1_BLO  139264
#define G1_BIAS 208896
#define G1_STAT 209920
#define G1_SMEM 214016

__global__ __launch_bounds__(256) void gemm1_mma(const float* __restrict__ b1, int M, int nb) {
    extern __shared__ char smem[];
    uint32_t sb = smem_u32(smem);
    int tid = threadIdx.x, w = tid >> 5, lane = tid & 31;
    float* b1s = (float*)(smem + G1_BIAS);
    b1s[tid] = __ldg(&b1[tid]);

    for (int u = tid; u < 4352; u += 256) {
        CP_ASYNC16(sb + G1_BHI + u * 16, (const char*)g_W1img_hi + u * 16);
        CP_ASYNC16(sb + G1_BLO + u * 16, (const char*)g_W1img_lo + u * 16);
    }
    {
        size_t abase = (size_t)blockIdx.x * TILEB;
        for (int u = tid; u < 2176; u += 256) {
            CP_ASYNC16(sb + G1_AHI + u * 16, (const char*)g_h0img_hi + abase + u * 16);
            CP_ASYNC16(sb + G1_ALO + u * 16, (const char*)g_h0img_lo + abase + u * 16);
        }
    }
    CP_COMMIT();

    int m0 = (w & 1) * 64, n0 = (w >> 1) * 64;
    int lr = lane & 7, mid = lane >> 3;
    uint32_t aoff = (uint32_t)((m0 + lr + ((mid & 1) << 3)) * 272 + ((mid >> 1) << 4));
    uint32_t boff = (uint32_t)((n0 + lr + ((mid >> 1) << 3)) * 272 + ((mid & 1) << 4));
    uint32_t aHb = sb + G1_AHI + aoff, aLb = sb + G1_ALO + aoff;
    uint32_t bHb = sb + G1_BHI + boff, bLb = sb + G1_BLO + boff;
    float* s_sum = (float*)(smem + G1_STAT);
    float* s_sq  = s_sum + 512;

    for (int rb = blockIdx.x; rb < nb; rb += gridDim.x) {
        int row0 = rb * 128;
        CP_WAIT0();
        __syncthreads();

        float acc[4][8][4];
        #pragma unroll
        for (int i = 0; i < 4; i++)
            #pragma unroll
            for (int j = 0; j < 8; j++)
                #pragma unroll
                for (int q = 0; q < 4; q++) acc[i][j][q] = 0.f;

        #pragma unroll
        for (int ks = 0; ks < 8; ks++) {
            uint32_t kb = ks << 5;
            uint32_t aH[4][4], aL[4][4];
            #pragma unroll
            for (int mb = 0; mb < 4; mb++) {
                ldsm_x4(aH[mb], aHb + mb * 4352 + kb);
                ldsm_x4(aL[mb], aLb + mb * 4352 + kb);
            }
            #pragma unroll
            for (int nbp = 0; nbp < 4; nbp++) {
                uint32_t bh[4], bl[4];
                ldsm_x4(bh, bHb + nbp * 4352 + kb);
                ldsm_x4(bl, bLb + nbp * 4352 + kb);
                #pragma unroll
                for (int mb = 0; mb < 4; mb++) {
                    mma16816(acc[mb][2*nbp],     aH[mb], bh);
                    mma16816(acc[mb][2*nbp],     aH[mb], bl);
                    mma16816(acc[mb][2*nbp],     aL[mb], bh);
                    mma16816(acc[mb][2*nbp + 1], aH[mb], bh + 2);
                    mma16816(acc[mb][2*nbp + 1], aH[mb], bl + 2);
                    mma16816(acc[mb][2*nbp + 1], aL[mb], bh + 2);
                }
            }
        }
        __syncthreads();

        int rbn = rb + gridDim.x;
        if (rbn < nb) {
            size_t abase = (size_t)rbn * TILEB;
            for (int u = tid; u < 2176; u += 256) {
                CP_ASYNC16(sb + G1_AHI + u * 16, (const char*)g_h0img_hi + abase + u * 16);
                CP_ASYNC16(sb + G1_ALO + u * 16, (const char*)g_h0img_lo + abase + u * 16);
            }
        }
        CP_COMMIT();

        int mtop = row0 + m0 + (lane >> 2);
        int nc = n0 + 2 * (lane & 3);
        float cs[8][2], cq[8][2];
        #pragma unroll
        for (int j = 0; j < 8; j++) { cs[j][0] = cs[j][1] = cq[j][0] = cq[j][1] = 0.f; }
        #pragma unroll
        for (int mb = 0; mb < 4; mb++) {
            int r0 = mtop + mb * 16;
            bool gd0 = r0 < M, gd1 = (r0 + 8) < M;
            #pragma unroll
            for (int nbq = 0; nbq < 8; nbq++) {
                int n = nc + nbq * 8;
                float bv0 = b1s[n], bv1 = b1s[n + 1];
                float o0 = acc[mb][nbq][0] + bv0, o1 = acc[mb][nbq][1] + bv1;
                float o2 = acc[mb][nbq][2] + bv0, o3 = acc[mb][nbq][3] + bv1;
                size_t r1 = (size_t)r0 * 256 + n;
                *(float2*)(g_h1 + r1)           = make_float2(o0, o1);
                *(float2*)(g_h1 + r1 + 8 * 256) = make_float2(o2, o3);
                cs[nbq][0] += (gd0 ? o0 : 0.f) + (gd1 ? o2 : 0.f);
                cs[nbq][1] += (gd0 ? o1 : 0.f) + (gd1 ? o3 : 0.f);
                cq[nbq][0] += (gd0 ? o0 * o0 : 0.f) + (gd1 ? o2 * o2 : 0.f);
                cq[nbq][1] += (gd0 ? o1 * o1 : 0.f) + (gd1 ? o3 * o3 : 0.f);
            }
        }
        #pragma unroll
        for (int nbq = 0; nbq < 8; nbq++) {
            #pragma unroll
            for (int o = 16; o >= 4; o >>= 1) {
                cs[nbq][0] += __shfl_down_sync(0xffffffffu, cs[nbq][0], o);
                cs[nbq][1] += __shfl_down_sync(0xffffffffu, cs[nbq][1], o);
                cq[nbq][0] += __shfl_down_sync(0xffffffffu, cq[nbq][0], o);
                cq[nbq][1] += __shfl_down_sync(0xffffffffu, cq[nbq][1], o);
            }
        }
        if (lane < 4) {
            #pragma unroll
            for (int nbq = 0; nbq < 8; nbq++) {
                int cl = nbq * 8 + lane * 2;
                s_sum[w * 64 + cl]     = cs[nbq][0];
                s_sum[w * 64 + cl + 1] = cs[nbq][1];
                s_sq [w * 64 + cl]     = cq[nbq][0];
                s_sq [w * 64 + cl + 1] = cq[nbq][1];
            }
        }
        __syncthreads();
        {
            int col = tid;
            int g = col >> 6, cl = col & 63;
            float ssum = s_sum[(2 * g) * 64 + cl] + s_sum[(2 * g + 1) * 64 + cl];
            float ssq  = s_sq [(2 * g) * 64 + cl] + s_sq [(2 * g + 1) * 64 + cl];
            g_bnpart[(size_t)rb * 512 + col]       = ssum;
            g_bnpart[(size_t)rb * 512 + 256 + col] = ssq;
        }
    }
}

// ---------------- BN finalize ------------------------------------------------
__global__ void bnfinal_kernel(const float* __restrict__ gamma,
                               const float* __restrict__ beta, int n, int nblk) {
    __shared__ float sh[512];
    int t = threadIdx.x;      // 512
    float s = 0.f;
    for (int b = 0; b < nblk; b++) s += g_bnpart[(size_t)b * 512 + t];
    sh[t] = s;
    __syncthreads();
    if (t < D2) {
        float inv_n = 1.f / (float)n;
        float mu  = sh[t] * inv_n;
        float var = sh[t + 256] * inv_n - mu * mu;
        float sc  = gamma[t] * rsqrtf(var + BN_EPS);
        g_bnscale[t] = sc;
        g_bnshift[t] = beta[t] - mu * sc;
    }
}

// ---------------- GEMM2 (persistent): out = x + relu(LN(relu(BN(h1))@W2+b2)) -
#define G2_AHI   0
#define G2_ALO   34816
#define G2_B     69632
#define G2_CST   0
#define G2_CONST 208896
#define G2_SMEM  212480

__global__ __launch_bounds__(256) void gemm2_mma(const float* __restrict__ b2,
                                                 const float* __restrict__ ln_gamma,
                                                 const float* __restrict__ ln_beta,
                                                 const float* __restrict__ x,
                                                 float* __restrict__ out, int M, int nb) {
    extern __shared__ char smem[];
    uint32_t sb = smem_u32(smem);
    int tid = threadIdx.x, w = tid >> 5, lane = tid & 31;

    float* s_sc = (float*)(smem + G2_CONST);
    float* s_sh = s_sc + 256;
    float* s_b2 = s_sh + 256;
    float* s_lg = s_b2 + 128;
    float* s_lb = s_lg + 128;
    s_sc[tid] = g_bnscale[tid];
    s_sh[tid] = g_bnshift[tid];
    if (tid < 128) {
        s_b2[tid] = __ldg(&b2[tid]);
        s_lg[tid] = __ldg(&ln_gamma[tid]);
        s_lb[tid] = __ldg(&ln_beta[tid]);
    }
    for (int u = tid; u < 2176; u += 256) {
        #pragma unroll
        for (int p = 0; p < 2; p++) {
            CP_ASYNC16(sb + G2_B + p * 69632 + u * 16,         (const char*)g_W2img_hi + p * TILEB + u * 16);
            CP_ASYNC16(sb + G2_B + p * 69632 + 34816 + u * 16, (const char*)g_W2img_lo + p * TILEB + u * 16);
        }
    }
    CP_COMMIT();

    int m0 = (w & 1) * 64, n0 = (w >> 1) * 32;
    int lr = lane & 7, mid = lane >> 3;
    uint32_t aoff = (uint32_t)((m0 + lr + ((mid & 1) << 3)) * 272 + ((mid >> 1) << 4));
    uint32_t boff = (uint32_t)((n0 + lr + ((mid >> 1) << 3)) * 272 + ((mid & 1) << 4));
    uint32_t aHb = sb + G2_AHI + aoff, aLb = sb + G2_ALO + aoff;

    for (int rb = blockIdx.x; rb < nb; rb += gridDim.x) {
        int row0 = rb * 128;
        float acc[4][4][4];
        #pragma unroll
        for (int i = 0; i < 4; i++)
            #pragma unroll
            for (int j = 0; j < 4; j++)
                #pragma unroll
                for (int q = 0; q < 4; q++) acc[i][j][q] = 0.f;

        for (int p = 0; p < 2; p++) {
            __syncthreads();
            for (int u = tid; u < 2048; u += 256) {
                int m = u >> 4, g = u & 15;
                int kc = (p << 7) + (g << 3);
                const float4* hr = (const float4*)(g_h1 + (size_t)(row0 + m) * 256 + kc);
                float4 q0 = hr[0], q1 = hr[1];
                float f[8] = {q0.x, q0.y, q0.z, q0.w, q1.x, q1.y, q1.z, q1.w};
                #pragma unroll
                for (int j = 0; j < 8; j++)
                    f[j] = fmaxf(fmaf(f[j], s_sc[kc + j], s_sh[kc + j]), 0.f);
                uint4 hv, lv; cvt8(f, hv, lv);
                int off = m * 272 + g * 16;
                *(uint4*)(smem + G2_AHI + off) = hv;
                *(uint4*)(smem + G2_ALO + off) = lv;
            }
            CP_WAIT0();
            __syncthreads();

            uint32_t bHb = sb + G2_B + p * 69632 + boff;
            uint32_t bLb = bHb + 34816;
            #pragma unroll
            for (int ks = 0; ks < 8; ks++) {
                uint32_t kb = ks << 5;
                uint32_t aH[4][4], aL[4][4];
                #pragma unroll
                for (int mb = 0; mb < 4; mb++) {
                    ldsm_x4(aH[mb], aHb + mb * 4352 + kb);
                    ldsm_x4(aL[mb], aLb + mb * 4352 + kb);
                }
                #pragma unroll
                for (int nbp = 0; nbp < 2; nbp++) {
                    uint32_t bh[4], bl[4];
                    ldsm_x4(bh, bHb + nbp * 4352 + kb);
                    ldsm_x4(bl, bLb + nbp * 4352 + kb);
                    #pragma unroll
                    for (int mb = 0; mb < 4; mb++) {
                        mma16816(acc[mb][2*nbp],     aH[mb], bh);
                        mma16816(acc[mb][2*nbp],     aH[mb], bl);
                        mma16816(acc[mb][2*nbp],     aL[mb], bh);
                        mma16816(acc[mb][2*nbp + 1], aH[mb], bh + 2);
                        mma16816(acc[mb][2*nbp + 1], aH[mb], bl + 2);
                        mma16816(acc[mb][2*nbp + 1], aL[mb], bh + 2);
                    }
                }
            }
        }
        __syncthreads();

        float* Cs = (float*)(smem + G2_CST);
        {
            int mtop = m0 + (lane >> 2), nc = n0 + 2 * (lane & 3);
            #pragma unroll
            for (int mb = 0; mb < 4; mb++) {
                #pragma unroll
                for (int nbq = 0; nbq < 4; nbq++) {
                    int n = nc + nbq * 8;
                    int rr = mtop + mb * 16;
                    *(float2*)(Cs + rr * 132 + n)       = make_float2(acc[mb][nbq][0], acc[mb][nbq][1]);
                    *(float2*)(Cs + (rr + 8) * 132 + n) = make_float2(acc[mb][nbq][2], acc[mb][nbq][3]);
                }
            }
        }
        __syncthreads();

        if (tid < 128) {
            int grow = row0 + tid;
            const float* cr = Cs + tid * 132;
            float sum = 0.f, sq = 0.f;
            #pragma unroll
            for (int c = 0; c < 128; c += 4) {
                float4 q = *(const float4*)(cr + c);
                float v0 = q.x + s_b2[c], v1 = q.y + s_b2[c+1];
                float v2 = q.z + s_b2[c+2], v3 = q.w + s_b2[c+3];
                sum += v0 + v1 + v2 + v3;
                sq  += v0*v0 + v1*v1 + v2*v2 + v3*v3;
            }
            float mu = sum * (1.f / D);
            float var = sq * (1.f / D) - mu * mu;
            float rr = rsqrtf(var + LN_EPS);
            if (grow < M) {
                const float4* xr = (const float4*)(x + (size_t)grow * D);
                float4* po = (float4*)(out + (size_t)grow * D);
                #pragma unroll
                for (int c = 0; c < 128; c += 4) {
                    float4 q = *(const float4*)(cr + c);
                    float4 xv = __ldg(xr + (c >> 2));
                    float4 o;
                    o.x = xv.x + fmaxf((q.x + s_b2[c]   - mu) * rr * s_lg[c]   + s_lb[c],   0.f);
                    o.y = xv.y + fmaxf((q.y + s_b2[c+1] - mu) * rr * s_lg[c+1] + s_lb[c+1], 0.f);
                    o.z = xv.z + fmaxf((q.z + s_b2[c+2] - mu) * rr * s_lg[c+2] + s_lb[c+2], 0.f);
                    o.w = xv.w + fmaxf((q.w + s_b2[c+3] - mu) * rr * s_lg[c+3] + s_lb[c+3], 0.f);
                    po[c >> 2] = o;
                }
            }
        }
    }
}

// ---------------- launcher ---------------------------------------------------
extern "C" void kernel_launch(void* const* d_in, const int* in_sizes, int n_in,
                              void* d_out, int out_size) {
    const float* x        = (const float*)d_in[0];
    const int*   ei       = (const int*)  d_in[1];
    const float* t_ptr    = (const float*)d_in[2];
    const float* W1       = (const float*)d_in[3];
    const float* b1       = (const float*)d_in[4];
    const float* bn_gamma = (const float*)d_in[5];
    const float* bn_beta  = (const float*)d_in[6];
    const float* W2       = (const float*)d_in[7];
    const float* b2       = (const float*)d_in[8];
    const float* ln_gamma = (const float*)d_in[9];
    const float* ln_beta  = (const float*)d_in[10];
    float* out = (float*)d_out;

    int n = in_sizes[0] / D;
    int e = in_sizes[1] / 2;
    const int* src = ei;
    const int* dst = ei + e;
    int nb = (n + 127) / 128;
    int npart = (n + 1023) / 1024;
    int gpers = nb < 152 ? nb : 152;
    int work1 = n * 32;
    if (work1 < e) work1 = e;
    if (work1 < 65536) work1 = 65536;
    int hb = (work1 + 1023) / 1024;

    cudaFuncSetAttribute(gemm1_mma, cudaFuncAttributeMaxDynamicSharedMemorySize, G1_SMEM);
    cudaFuncSetAttribute(gemm2_mma, cudaFuncAttributeMaxDynamicSharedMemorySize, G2_SMEM);

    k1_init_hist<<<hb, 1024>>>(W1, W2, x, t_ptr, dst, e, n, npart);
    scan_local_kernel<<<npart, 1024>>>(n);
    scatter_kernel<<<(e + 255) / 256, 256>>>(src, dst, e);
    agg_kernel<<<(n * 32 + 255) / 256, 256>>>(x, n);
    gemm1_mma<<<gpers, 256, G1_SMEM>>>(b1, n, nb);
    bnfinal_kernel<<<1, 512>>>(bn_gamma, bn_beta, n, nb);
    gemm2_mma<<<gpers, 256, G2_SMEM>>>(b2, ln_gamma, ln_beta, x, out, n, nb);
}